// round 1
// baseline (speedup 1.0000x reference)
#include <cuda_runtime.h>
#include <math.h>

// Problem constants
constexpr int CB  = 16;    // batch
constexpr int CN  = 512;   // seq len
constexpr int CD  = 512;   // model dim
constexpr int CH  = 8;     // heads
constexpr int CHD = 64;    // head dim
constexpr int CK  = 16;    // top-k
constexpr int ROWS = CB * CN;       // 8192
constexpr int DFF  = 4 * CD;        // 2048

// Scratch (device globals — no allocations allowed)
__device__ float g_xn [ROWS * CD];
__device__ float g_q  [ROWS * CD];
__device__ float g_k  [ROWS * CD];
__device__ float g_v  [ROWS * CD];
__device__ float g_att[ROWS * CD];
__device__ float g_x1 [ROWS * CD];
__device__ float g_ffh[ROWS * DFF];
__device__ float g_lg [(size_t)CB * CH * CN * CN];   // 134 MB logits

// ---------------------------------------------------------------------------
// LayerNorm: one block per row, 256 threads, two-pass (matches ref numerics)
// ---------------------------------------------------------------------------
__global__ void ln_kernel(const float* __restrict__ x, const float* __restrict__ g,
                          const float* __restrict__ be, float* __restrict__ out)
{
    const int row = blockIdx.x;
    const float* xr = x + (size_t)row * CD;
    const int t = threadIdx.x;  // 256
    float v0 = xr[t], v1 = xr[t + 256];

    __shared__ float red[256];
    red[t] = v0 + v1;
    __syncthreads();
    #pragma unroll
    for (int o = 128; o > 0; o >>= 1) { if (t < o) red[t] += red[t + o]; __syncthreads(); }
    const float mean = red[0] * (1.0f / CD);
    __syncthreads();

    const float d0 = v0 - mean, d1 = v1 - mean;
    red[t] = d0 * d0 + d1 * d1;
    __syncthreads();
    #pragma unroll
    for (int o = 128; o > 0; o >>= 1) { if (t < o) red[t] += red[t + o]; __syncthreads(); }
    const float var = red[0] * (1.0f / CD);
    const float rs  = rsqrtf(var + 1e-5f);

    out[(size_t)row * CD + t]       = d0 * rs * g[t]       + be[t];
    out[(size_t)row * CD + t + 256] = d1 * rs * g[t + 256] + be[t + 256];
}

// ---------------------------------------------------------------------------
// Tiled fp32 SGEMM: C[M,N] = A[M,K] @ B[K,N] + epilogue.
// BM=BN=128, BK=8, 256 threads, 8x8 per thread. All dims divisible (no guards).
// ---------------------------------------------------------------------------
enum { EP_BIAS = 0, EP_BIAS_RES = 1, EP_GELU = 2 };

template <int EPI>
__global__ void __launch_bounds__(256, 2)
sgemm128(const float* __restrict__ A, const float* __restrict__ Bm,
         const float* __restrict__ bias, const float* __restrict__ res,
         float* __restrict__ C, int M, int N, int Kd)
{
    __shared__ float As[8][128];
    __shared__ float Bs[8][128];

    const int tid = threadIdx.x;
    const int tx = tid & 15, ty = tid >> 4;
    const int arow = tid >> 1, acol = (tid & 1) * 4;
    const int brow = tid >> 5, bcol = (tid & 31) * 4;

    const int rowb = blockIdx.y * 128;
    const int colb = blockIdx.x * 128;

    const float* Aptr = A + (size_t)(rowb + arow) * Kd + acol;
    const float* Bptr = Bm + (size_t)brow * N + colb + bcol;

    float acc[8][8];
    #pragma unroll
    for (int i = 0; i < 8; i++)
        #pragma unroll
        for (int j = 0; j < 8; j++) acc[i][j] = 0.0f;

    for (int k0 = 0; k0 < Kd; k0 += 8) {
        const float4 av = *(const float4*)(Aptr + k0);
        const float4 bv = *(const float4*)(Bptr + (size_t)k0 * N);
        __syncthreads();
        As[acol + 0][arow] = av.x;
        As[acol + 1][arow] = av.y;
        As[acol + 2][arow] = av.z;
        As[acol + 3][arow] = av.w;
        *(float4*)&Bs[brow][bcol] = bv;
        __syncthreads();

        #pragma unroll
        for (int kk = 0; kk < 8; kk++) {
            const float4 a0 = *(const float4*)&As[kk][ty * 4];
            const float4 a1 = *(const float4*)&As[kk][64 + ty * 4];
            const float4 b0 = *(const float4*)&Bs[kk][tx * 4];
            const float4 b1 = *(const float4*)&Bs[kk][64 + tx * 4];
            const float a[8] = {a0.x, a0.y, a0.z, a0.w, a1.x, a1.y, a1.z, a1.w};
            const float b[8] = {b0.x, b0.y, b0.z, b0.w, b1.x, b1.y, b1.z, b1.w};
            #pragma unroll
            for (int i = 0; i < 8; i++)
                #pragma unroll
                for (int j = 0; j < 8; j++)
                    acc[i][j] = fmaf(a[i], b[j], acc[i][j]);
        }
    }

    #pragma unroll
    for (int i = 0; i < 8; i++) {
        const int r = rowb + ((i < 4) ? (ty * 4 + i) : (60 + ty * 4 + i));
        #pragma unroll
        for (int half = 0; half < 2; half++) {
            const int c = colb + half * 64 + tx * 4;
            float4 v;
            v.x = acc[i][half * 4 + 0] + bias[c + 0];
            v.y = acc[i][half * 4 + 1] + bias[c + 1];
            v.z = acc[i][half * 4 + 2] + bias[c + 2];
            v.w = acc[i][half * 4 + 3] + bias[c + 3];
            if (EPI == EP_BIAS_RES) {
                const float4 rv = *(const float4*)(res + (size_t)r * N + c);
                v.x += rv.x; v.y += rv.y; v.z += rv.z; v.w += rv.w;
            }
            if (EPI == EP_GELU) {
                v.x = 0.5f * v.x * (1.0f + erff(v.x * 0.70710678118654752f));
                v.y = 0.5f * v.y * (1.0f + erff(v.y * 0.70710678118654752f));
                v.z = 0.5f * v.z * (1.0f + erff(v.z * 0.70710678118654752f));
                v.w = 0.5f * v.w * (1.0f + erff(v.w * 0.70710678118654752f));
            }
            *(float4*)(C + (size_t)r * N + c) = v;
        }
    }
}

// ---------------------------------------------------------------------------
// Batched QK^T (NT), fused scale + relative positional bias.
// Per (b,h): C[512,512] = Q_bh[512,64] @ K_bh[512,64]^T * 0.125 + rel bias.
// BM=BN=64, BK=16, 256 threads, 4x4 per thread. grid (8, 8, 128)
// ---------------------------------------------------------------------------
__global__ void __launch_bounds__(256)
qk_kernel(const float* __restrict__ Q, const float* __restrict__ Kt,
          const float* __restrict__ rel, float* __restrict__ out)
{
    const int bh = blockIdx.z;
    const int b = bh >> 3, h = bh & 7;
    const float* Ab = Q  + (size_t)b * CN * CD + h * CHD;
    const float* Bb = Kt + (size_t)b * CN * CD + h * CHD;
    float* Cb = out + (size_t)bh * CN * CN;

    __shared__ float As[16][68];
    __shared__ float Bs[16][68];

    const int tid = threadIdx.x;
    const int tx = tid & 15, ty = tid >> 4;
    const int lrow = tid >> 2, lcol = (tid & 3) * 4;

    float acc[4][4];
    #pragma unroll
    for (int i = 0; i < 4; i++)
        #pragma unroll
        for (int j = 0; j < 4; j++) acc[i][j] = 0.0f;

    const int rowb = blockIdx.y * 64;   // query n
    const int colb = blockIdx.x * 64;   // key m

    for (int k0 = 0; k0 < CHD; k0 += 16) {
        const float4 av = *(const float4*)(Ab + (size_t)(rowb + lrow) * CD + k0 + lcol);
        const float4 bv = *(const float4*)(Bb + (size_t)(colb + lrow) * CD + k0 + lcol);
        __syncthreads();
        As[lcol + 0][lrow] = av.x; As[lcol + 1][lrow] = av.y;
        As[lcol + 2][lrow] = av.z; As[lcol + 3][lrow] = av.w;
        Bs[lcol + 0][lrow] = bv.x; Bs[lcol + 1][lrow] = bv.y;
        Bs[lcol + 2][lrow] = bv.z; Bs[lcol + 3][lrow] = bv.w;
        __syncthreads();

        #pragma unroll
        for (int kk = 0; kk < 16; kk++) {
            const float4 a = *(const float4*)&As[kk][ty * 4];
            const float4 bq = *(const float4*)&Bs[kk][tx * 4];
            const float aa[4] = {a.x, a.y, a.z, a.w};
            const float bb[4] = {bq.x, bq.y, bq.z, bq.w};
            #pragma unroll
            for (int i = 0; i < 4; i++)
                #pragma unroll
                for (int j = 0; j < 4; j++)
                    acc[i][j] = fmaf(aa[i], bb[j], acc[i][j]);
        }
    }

    #pragma unroll
    for (int i = 0; i < 4; i++) {
        const int gm = rowb + ty * 4 + i;
        #pragma unroll
        for (int j = 0; j < 4; j++) {
            const int gn = colb + tx * 4 + j;
            Cb[(size_t)gm * CN + gn] =
                acc[i][j] * 0.125f + rel[(size_t)(gn - gm + 511) * CH + h];
        }
    }
}

// ---------------------------------------------------------------------------
// Top-16 + softmax + sparse A@V. One block per (b,h,n), 128 threads.
// 16 iterations of block-wide argmax with invalidation (distinct indices).
// ---------------------------------------------------------------------------
__global__ void __launch_bounds__(128)
topk_attn(const float* __restrict__ logits, const float* __restrict__ V,
          float* __restrict__ out)
{
    const int n = blockIdx.x, h = blockIdx.y, b = blockIdx.z;
    const int t = threadIdx.x;  // 128
    const float* row = logits + (((size_t)(b * CH + h)) * CN + n) * CN;

    float lv[4];
    #pragma unroll
    for (int j = 0; j < 4; j++) lv[j] = row[t + 128 * j];

    __shared__ float wv[4];
    __shared__ int   wi[4];
    __shared__ float topv[CK];
    __shared__ int   topi[CK];
    __shared__ float ex[CK];

    for (int it = 0; it < CK; it++) {
        float v = lv[0]; int idx = t;
        #pragma unroll
        for (int j = 1; j < 4; j++)
            if (lv[j] > v) { v = lv[j]; idx = t + 128 * j; }
        #pragma unroll
        for (int o = 16; o > 0; o >>= 1) {
            const float v2 = __shfl_xor_sync(0xffffffffu, v, o);
            const int   i2 = __shfl_xor_sync(0xffffffffu, idx, o);
            if (v2 > v) { v = v2; idx = i2; }
        }
        if ((t & 31) == 0) { wv[t >> 5] = v; wi[t >> 5] = idx; }
        __syncthreads();
        float bv = wv[0]; int bi = wi[0];
        #pragma unroll
        for (int w = 1; w < 4; w++)
            if (wv[w] > bv) { bv = wv[w]; bi = wi[w]; }
        if (t == 0) { topv[it] = bv; topi[it] = bi; }
        if (t == (bi & 127)) lv[bi >> 7] = -3.0e38f;  // invalidate selected
        __syncthreads();
    }

    // softmax over the 16 selected (topv[0] is the global max)
    if (t < CK) ex[t] = expf(topv[t] - topv[0]);
    __syncthreads();
    float s = 0.0f;
    #pragma unroll
    for (int i = 0; i < CK; i++) s += ex[i];
    const float inv = 1.0f / s;

    if (t < CHD) {
        float acc = 0.0f;
        #pragma unroll
        for (int i = 0; i < CK; i++)
            acc += ex[i] * V[((size_t)(b * CN) + topi[i]) * CD + h * CHD + t];
        out[((size_t)(b * CN) + n) * CD + h * CHD + t] = acc * inv;
    }
}

// ---------------------------------------------------------------------------
// Launch
// ---------------------------------------------------------------------------
extern "C" void kernel_launch(void* const* d_in, const int* in_sizes, int n_in,
                              void* d_out, int out_size)
{
    const float* x    = (const float*)d_in[0];
    const float* wq   = (const float*)d_in[1];
    const float* bq   = (const float*)d_in[2];
    const float* wk   = (const float*)d_in[3];
    const float* bk   = (const float*)d_in[4];
    const float* wv   = (const float*)d_in[5];
    const float* bv   = (const float*)d_in[6];
    const float* wo   = (const float*)d_in[7];
    const float* bo   = (const float*)d_in[8];
    const float* g1   = (const float*)d_in[9];
    const float* be1  = (const float*)d_in[10];
    const float* g2   = (const float*)d_in[11];
    const float* be2  = (const float*)d_in[12];
    const float* w1   = (const float*)d_in[13];
    const float* bf1  = (const float*)d_in[14];
    const float* w2   = (const float*)d_in[15];
    const float* bf2  = (const float*)d_in[16];
    const float* rel  = (const float*)d_in[17];
    float* out = (float*)d_out;

    float *xn, *q, *k, *v, *lg, *att, *x1, *ffh;
    cudaGetSymbolAddress((void**)&xn,  g_xn);
    cudaGetSymbolAddress((void**)&q,   g_q);
    cudaGetSymbolAddress((void**)&k,   g_k);
    cudaGetSymbolAddress((void**)&v,   g_v);
    cudaGetSymbolAddress((void**)&lg,  g_lg);
    cudaGetSymbolAddress((void**)&att, g_att);
    cudaGetSymbolAddress((void**)&x1,  g_x1);
    cudaGetSymbolAddress((void**)&ffh, g_ffh);

    // 1. LN1
    ln_kernel<<<ROWS, 256>>>(x, g1, be1, xn);

    // 2. QKV projections
    sgemm128<EP_BIAS><<<dim3(CD / 128, ROWS / 128), 256>>>(xn, wq, bq, nullptr, q,  ROWS, CD, CD);
    sgemm128<EP_BIAS><<<dim3(CD / 128, ROWS / 128), 256>>>(xn, wk, bk, nullptr, k,  ROWS, CD, CD);
    sgemm128<EP_BIAS><<<dim3(CD / 128, ROWS / 128), 256>>>(xn, wv, bv, nullptr, v,  ROWS, CD, CD);

    // 3. Logits = scale * Q K^T + rel bias (batched over b,h)
    qk_kernel<<<dim3(CN / 64, CN / 64, CB * CH), 256>>>(q, k, rel, lg);

    // 4. top-16 + softmax + sparse A@V
    topk_attn<<<dim3(CN, CH, CB), 128>>>(lg, v, att);

    // 5. out proj + residual
    sgemm128<EP_BIAS_RES><<<dim3(CD / 128, ROWS / 128), 256>>>(att, wo, bo, x, x1, ROWS, CD, CD);

    // 6. LN2 (reuse xn)
    ln_kernel<<<ROWS, 256>>>(x1, g2, be2, xn);

    // 7. FFN
    sgemm128<EP_GELU><<<dim3(DFF / 128, ROWS / 128), 256>>>(xn, w1, bf1, nullptr, ffh, ROWS, DFF, CD);
    sgemm128<EP_BIAS_RES><<<dim3(CD / 128, ROWS / 128), 256>>>(ffh, w2, bf2, x1, out, ROWS, CD, DFF);
}

// round 8
// speedup vs baseline: 1.4038x; 1.4038x over previous
#include <cuda_runtime.h>
#include <cuda_bf16.h>
#include <cstdint>
#include <math.h>

// Problem constants
constexpr int CB  = 16;
constexpr int CN  = 512;
constexpr int CD  = 512;
constexpr int CH  = 8;
constexpr int CHD = 64;
constexpr int CK  = 16;
constexpr int ROWS = CB * CN;   // 8192
constexpr int DFF  = 4 * CD;    // 2048

// Scratch (device globals — no allocations allowed)
__device__ float g_xn [ROWS * CD];
__device__ float g_q  [ROWS * CD];
__device__ float g_k  [ROWS * CD];
__device__ float g_v  [ROWS * CD];
__device__ float g_att[ROWS * CD];
__device__ float g_x1 [ROWS * CD];
__device__ float g_ffh[ROWS * DFF];
__device__ float g_lg [(size_t)CB * CH * CN * CN];
// transposed weights [N, K] K-major (B operand, "col" layout for mma)
__device__ float g_wqt[CD * CD];
__device__ float g_wkt[CD * CD];
__device__ float g_wvt[CD * CD];
__device__ float g_wot[CD * CD];
__device__ float g_w1t[DFF * CD];
__device__ float g_w2t[CD * DFF];

// ---------------------------------------------------------------------------
// PTX helpers (sm_80+ features only — compiles at plain target sm_103)
// ---------------------------------------------------------------------------
__device__ __forceinline__ uint32_t smem_u32(const void* p) {
    uint32_t a;
    asm("{ .reg .u64 t; cvta.to.shared.u64 t, %1; cvt.u32.u64 %0, t; }" : "=r"(a) : "l"(p));
    return a;
}
__device__ __forceinline__ void ldsm4(uint32_t* r, uint32_t addr) {
    asm volatile("ldmatrix.sync.aligned.m8n8.x4.shared.b16 {%0,%1,%2,%3}, [%4];"
                 : "=r"(r[0]), "=r"(r[1]), "=r"(r[2]), "=r"(r[3]) : "r"(addr));
}
__device__ __forceinline__ void mma_bf16(float* d, const uint32_t* a,
                                         uint32_t b0, uint32_t b1) {
    asm volatile("mma.sync.aligned.m16n8k16.row.col.f32.bf16.bf16.f32 "
                 "{%0,%1,%2,%3}, {%4,%5,%6,%7}, {%8,%9}, {%0,%1,%2,%3};"
                 : "+f"(d[0]), "+f"(d[1]), "+f"(d[2]), "+f"(d[3])
                 : "r"(a[0]), "r"(a[1]), "r"(a[2]), "r"(a[3]), "r"(b0), "r"(b1));
}
// pack two floats into bf16x2: low half = e0 (lower k), high half = e1
__device__ __forceinline__ uint32_t packbf(float e0, float e1) {
    uint32_t r;
    asm("cvt.rn.bf16x2.f32 %0, %1, %2;" : "=r"(r) : "f"(e1), "f"(e0));
    return r;
}
__device__ __forceinline__ float bf_hi(float x) {
    // round-to-nearest bf16, back to float
    __nv_bfloat16 h = __float2bfloat16_rn(x);
    return __bfloat162float(h);
}

// ---------------------------------------------------------------------------
// bf16x3 tensor-core GEMM:  C[M,N] = A[M,K](row) @ B[N,K](row, = B^T) + epi
// Each fp32 operand split hi+lo (bf16); acc += hi*hi + hi*lo + lo*hi (fp32).
// Block 128x128, BK=32, 256 threads, 8 warps 4x2; warp tile 32x64.
// SMEM row (128B) = [hi: 32 bf16 | lo: 32 bf16], SW128 swizzle.
// Stages: [A0][A1][B0][B1] 16KB each = 64KB dynamic.
// ---------------------------------------------------------------------------
enum { EP_BIAS = 0, EP_BIAS_RES = 1, EP_GELU = 2, EP_QK = 3 };

constexpr int BK = 32;
constexpr int STAGE = 128 * 128;             // 16384 B per tile buffer
constexpr int GEMM_SMEM = 4 * STAGE;         // 65536 B

template <int EPI>
__global__ void __launch_bounds__(256)
gemm_mma(const float* __restrict__ A, const float* __restrict__ B,
         const float* __restrict__ bias, const float* __restrict__ res,
         float* __restrict__ C, int lda, int ldb, int ldc, int K,
         const float* __restrict__ rel)
{
    extern __shared__ char smraw[];
    const uint32_t sb = smem_u32(smraw);

    const int tid = threadIdx.x;
    const int lane = tid & 31, wid = tid >> 5;
    const int wm = wid >> 1, wn = wid & 1;       // 4 x 2 warp grid

    const int rowb = blockIdx.y * 128;
    const int colb = blockIdx.x * 128;

    const float* Ag = A;
    const float* Bg = B;
    float* Cg = C;
    int h = 0;
    if (EPI == EP_QK) {
        const int bh = blockIdx.z;
        const int b = bh >> 3; h = bh & 7;
        Ag = A + (size_t)b * CN * CD + h * CHD;
        Bg = B + (size_t)b * CN * CD + h * CHD;
        Cg = C + (size_t)bh * CN * CN;
    }

    // ---- gmem load mapping: 2 threads per row, 16 consecutive floats each
    const int grow = tid >> 1;                   // 0..127
    const int gcol = (tid & 1) * 16;             // 0 or 16 (floats)
    const float* Aptr = Ag + (size_t)(grow + rowb) * lda + gcol;
    const float* Bptr = Bg + (size_t)(grow + colb) * ldb + gcol;

    // swizzled STS byte offsets: hi at [gcol*2, +32), lo at [64+gcol*2, +32)
    uint32_t shi[2], slo[2];
    #pragma unroll
    for (int j = 0; j < 2; j++) {
        uint32_t o1 = (uint32_t)grow * 128u + (uint32_t)gcol * 2u + j * 16u;
        uint32_t o2 = o1 + 64u;
        shi[j] = o1 ^ ((o1 >> 3) & 0x70u);
        slo[j] = o2 ^ ((o2 >> 3) & 0x70u);
    }

    // ---- ldmatrix per-lane addressing
    const int lrow16 = lane & 15;
    const uint32_t cg16 = (uint32_t)(lane >> 4) * 16u;   // k-chunk within frag
    uint32_t rbA[2], rsA[2], rbB[4], rsB[4];
    #pragma unroll
    for (int mt = 0; mt < 2; mt++) {
        const int r = wm * 32 + mt * 16 + lrow16;
        rbA[mt] = (uint32_t)r * 128u;
        rsA[mt] = (uint32_t)(r & 7) << 4;
    }
    #pragma unroll
    for (int np = 0; np < 4; np++) {
        const int r = wn * 64 + np * 16 + lrow16;
        rbB[np] = (uint32_t)r * 128u;
        rsB[np] = (uint32_t)(r & 7) << 4;
    }

    float acc[2][8][4];
    #pragma unroll
    for (int mt = 0; mt < 2; mt++)
        #pragma unroll
        for (int nt = 0; nt < 8; nt++)
            #pragma unroll
            for (int i = 0; i < 4; i++) acc[mt][nt][i] = 0.0f;

    const int NIT = K / BK;
    float4 pa[4], pb[4];

    // split 16 floats -> 8 hi uint32 + 8 lo uint32, store to stage
    auto split_sts = [&](uint32_t base, const float4* p, const uint32_t* oh,
                         const uint32_t* ol) {
        uint32_t hi[8], lo[8];
        #pragma unroll
        for (int j = 0; j < 4; j++) {
            const float4 v = p[j];
            float hx = bf_hi(v.x), hy = bf_hi(v.y), hz = bf_hi(v.z), hw = bf_hi(v.w);
            hi[j * 2 + 0] = packbf(v.x, v.y);      // rn bf16 of x,y
            hi[j * 2 + 1] = packbf(v.z, v.w);
            lo[j * 2 + 0] = packbf(v.x - hx, v.y - hy);
            lo[j * 2 + 1] = packbf(v.z - hz, v.w - hw);
        }
        *(uint4*)(smraw + (base + oh[0] - sb)) = *(uint4*)&hi[0];
        *(uint4*)(smraw + (base + oh[1] - sb)) = *(uint4*)&hi[4];
        *(uint4*)(smraw + (base + ol[0] - sb)) = *(uint4*)&lo[0];
        *(uint4*)(smraw + (base + ol[1] - sb)) = *(uint4*)&lo[4];
    };

    // preload stage 0
    #pragma unroll
    for (int j = 0; j < 4; j++) {
        pa[j] = *(const float4*)(Aptr + j * 4);
        pb[j] = *(const float4*)(Bptr + j * 4);
    }
    split_sts(sb, pa, shi, slo);
    split_sts(sb + 2 * STAGE, pb, shi, slo);
    __syncthreads();

    for (int it = 0; it < NIT; it++) {
        const int buf = it & 1;
        const uint32_t abase = sb + (uint32_t)buf * STAGE;
        const uint32_t bbase = sb + 2 * STAGE + (uint32_t)buf * STAGE;

        if (it + 1 < NIT) {
            const float* ap = Aptr + (it + 1) * BK;
            const float* bp = Bptr + (it + 1) * BK;
            #pragma unroll
            for (int j = 0; j < 4; j++) {
                pa[j] = *(const float4*)(ap + j * 4);
                pb[j] = *(const float4*)(bp + j * 4);
            }
        }

        #pragma unroll
        for (int ks = 0; ks < 2; ks++) {             // 2 x k16
            const uint32_t kc = (uint32_t)ks * 32u + cg16;
            uint32_t ah[2][4], al[2][4];
            #pragma unroll
            for (int mt = 0; mt < 2; mt++) {
                ldsm4(ah[mt], abase + rbA[mt] + (kc ^ rsA[mt]));
                ldsm4(al[mt], abase + rbA[mt] + ((kc + 64u) ^ rsA[mt]));
            }
            #pragma unroll
            for (int np = 0; np < 4; np++) {
                uint32_t bh[4], bl[4];
                ldsm4(bh, bbase + rbB[np] + (kc ^ rsB[np]));
                ldsm4(bl, bbase + rbB[np] + ((kc + 64u) ^ rsB[np]));
                #pragma unroll
                for (int mt = 0; mt < 2; mt++) {
                    mma_bf16(acc[mt][np * 2 + 0], ah[mt], bh[0], bh[2]);
                    mma_bf16(acc[mt][np * 2 + 1], ah[mt], bh[1], bh[3]);
                    mma_bf16(acc[mt][np * 2 + 0], ah[mt], bl[0], bl[2]);
                    mma_bf16(acc[mt][np * 2 + 1], ah[mt], bl[1], bl[3]);
                    mma_bf16(acc[mt][np * 2 + 0], al[mt], bh[0], bh[2]);
                    mma_bf16(acc[mt][np * 2 + 1], al[mt], bh[1], bh[3]);
                }
            }
        }

        if (it + 1 < NIT) {
            const uint32_t nb = (uint32_t)(buf ^ 1) * STAGE;
            __syncthreads();   // all warps done reading buf^1 from prior iter
            split_sts(sb + nb, pa, shi, slo);
            split_sts(sb + 2 * STAGE + nb, pb, shi, slo);
            __syncthreads();
        }
    }

    // ---- epilogue
    #pragma unroll
    for (int mt = 0; mt < 2; mt++) {
        #pragma unroll
        for (int half = 0; half < 2; half++) {
            const int r = rowb + wm * 32 + mt * 16 + (lane >> 2) + half * 8;
            float* crow = Cg + (size_t)r * ldc;
            const float* rrow = (EPI == EP_BIAS_RES) ? res + (size_t)r * ldc : nullptr;
            #pragma unroll
            for (int nt = 0; nt < 8; nt++) {
                const int c = colb + wn * 64 + nt * 8 + (lane & 3) * 2;
                float vx = acc[mt][nt][half * 2 + 0];
                float vy = acc[mt][nt][half * 2 + 1];
                if (EPI == EP_QK) {
                    vx = vx * 0.125f + __ldg(&rel[(size_t)(c     - r + 511) * CH + h]);
                    vy = vy * 0.125f + __ldg(&rel[(size_t)(c + 1 - r + 511) * CH + h]);
                } else {
                    vx += bias[c];
                    vy += bias[c + 1];
                    if (EPI == EP_BIAS_RES) { vx += rrow[c]; vy += rrow[c + 1]; }
                    if (EPI == EP_GELU) {
                        vx = 0.5f * vx * (1.0f + erff(vx * 0.70710678118654752f));
                        vy = 0.5f * vy * (1.0f + erff(vy * 0.70710678118654752f));
                    }
                }
                float2 o; o.x = vx; o.y = vy;
                *(float2*)(crow + c) = o;
            }
        }
    }
}

// ---------------------------------------------------------------------------
// Weight transpose: out[c*R + r] = in[r*C + c]
// ---------------------------------------------------------------------------
__global__ void transpose_k(const float* __restrict__ in, float* __restrict__ out,
                            int R, int C)
{
    __shared__ float t[32][33];
    const int c0 = blockIdx.x * 32, r0 = blockIdx.y * 32;
    const int x = threadIdx.x, y = threadIdx.y;
    #pragma unroll
    for (int i = 0; i < 32; i += 8)
        t[y + i][x] = in[(size_t)(r0 + y + i) * C + c0 + x];
    __syncthreads();
    #pragma unroll
    for (int i = 0; i < 32; i += 8)
        out[(size_t)(c0 + y + i) * R + r0 + x] = t[x][y + i];
}

// ---------------------------------------------------------------------------
// LayerNorm
// ---------------------------------------------------------------------------
__global__ void ln_kernel(const float* __restrict__ x, const float* __restrict__ g,
                          const float* __restrict__ be, float* __restrict__ out)
{
    const int row = blockIdx.x;
    const float* xr = x + (size_t)row * CD;
    const int t = threadIdx.x;
    float v0 = xr[t], v1 = xr[t + 256];

    __shared__ float red[256];
    red[t] = v0 + v1;
    __syncthreads();
    #pragma unroll
    for (int o = 128; o > 0; o >>= 1) { if (t < o) red[t] += red[t + o]; __syncthreads(); }
    const float mean = red[0] * (1.0f / CD);
    __syncthreads();

    const float d0 = v0 - mean, d1 = v1 - mean;
    red[t] = d0 * d0 + d1 * d1;
    __syncthreads();
    #pragma unroll
    for (int o = 128; o > 0; o >>= 1) { if (t < o) red[t] += red[t + o]; __syncthreads(); }
    const float var = red[0] * (1.0f / CD);
    const float rs  = rsqrtf(var + 1e-5f);

    out[(size_t)row * CD + t]       = d0 * rs * g[t]       + be[t];
    out[(size_t)row * CD + t + 256] = d1 * rs * g[t + 256] + be[t + 256];
}

// ---------------------------------------------------------------------------
// Top-16 + softmax + sparse A@V. One block per (b,h,n), 128 threads.
// ---------------------------------------------------------------------------
__global__ void __launch_bounds__(128)
topk_attn(const float* __restrict__ logits, const float* __restrict__ V,
          float* __restrict__ out)
{
    const int n = blockIdx.x, h = blockIdx.y, b = blockIdx.z;
    const int t = threadIdx.x;
    const float* row = logits + (((size_t)(b * CH + h)) * CN + n) * CN;

    float lv[4];
    #pragma unroll
    for (int j = 0; j < 4; j++) lv[j] = row[t + 128 * j];

    __shared__ float wv[4];
    __shared__ int   wi[4];
    __shared__ float topv[CK];
    __shared__ int   topi[CK];
    __shared__ float ex[CK];

    for (int it = 0; it < CK; it++) {
        float v = lv[0]; int idx = t;
        #pragma unroll
        for (int j = 1; j < 4; j++)
            if (lv[j] > v) { v = lv[j]; idx = t + 128 * j; }
        #pragma unroll
        for (int o = 16; o > 0; o >>= 1) {
            const float v2 = __shfl_xor_sync(0xffffffffu, v, o);
            const int   i2 = __shfl_xor_sync(0xffffffffu, idx, o);
            if (v2 > v) { v = v2; idx = i2; }
        }
        if ((t & 31) == 0) { wv[t >> 5] = v; wi[t >> 5] = idx; }
        __syncthreads();
        float bv = wv[0]; int bi = wi[0];
        #pragma unroll
        for (int w = 1; w < 4; w++)
            if (wv[w] > bv) { bv = wv[w]; bi = wi[w]; }
        if (t == 0) { topv[it] = bv; topi[it] = bi; }
        if (t == (bi & 127)) lv[bi >> 7] = -3.0e38f;
        __syncthreads();
    }

    if (t < CK) ex[t] = expf(topv[t] - topv[0]);
    __syncthreads();
    float s = 0.0f;
    #pragma unroll
    for (int i = 0; i < CK; i++) s += ex[i];
    const float inv = 1.0f / s;

    if (t < CHD) {
        float acc = 0.0f;
        #pragma unroll
        for (int i = 0; i < CK; i++)
            acc += ex[i] * V[((size_t)(b * CN) + topi[i]) * CD + h * CHD + t];
        out[((size_t)(b * CN) + n) * CD + h * CHD + t] = acc * inv;
    }
}

// ---------------------------------------------------------------------------
// Launch
// ---------------------------------------------------------------------------
extern "C" void kernel_launch(void* const* d_in, const int* in_sizes, int n_in,
                              void* d_out, int out_size)
{
    const float* x    = (const float*)d_in[0];
    const float* wq   = (const float*)d_in[1];
    const float* bq   = (const float*)d_in[2];
    const float* wk   = (const float*)d_in[3];
    const float* bk   = (const float*)d_in[4];
    const float* wv   = (const float*)d_in[5];
    const float* bv   = (const float*)d_in[6];
    const float* wo   = (const float*)d_in[7];
    const float* bo   = (const float*)d_in[8];
    const float* g1   = (const float*)d_in[9];
    const float* be1  = (const float*)d_in[10];
    const float* g2   = (const float*)d_in[11];
    const float* be2  = (const float*)d_in[12];
    const float* w1   = (const float*)d_in[13];
    const float* bf1  = (const float*)d_in[14];
    const float* w2   = (const float*)d_in[15];
    const float* bf2  = (const float*)d_in[16];
    const float* rel  = (const float*)d_in[17];
    float* out = (float*)d_out;

    float *xn, *q, *k, *v, *lg, *att, *x1, *ffh;
    float *wqt, *wkt, *wvt, *wot, *w1t, *w2t;
    cudaGetSymbolAddress((void**)&xn,  g_xn);
    cudaGetSymbolAddress((void**)&q,   g_q);
    cudaGetSymbolAddress((void**)&k,   g_k);
    cudaGetSymbolAddress((void**)&v,   g_v);
    cudaGetSymbolAddress((void**)&lg,  g_lg);
    cudaGetSymbolAddress((void**)&att, g_att);
    cudaGetSymbolAddress((void**)&x1,  g_x1);
    cudaGetSymbolAddress((void**)&ffh, g_ffh);
    cudaGetSymbolAddress((void**)&wqt, g_wqt);
    cudaGetSymbolAddress((void**)&wkt, g_wkt);
    cudaGetSymbolAddress((void**)&wvt, g_wvt);
    cudaGetSymbolAddress((void**)&wot, g_wot);
    cudaGetSymbolAddress((void**)&w1t, g_w1t);
    cudaGetSymbolAddress((void**)&w2t, g_w2t);

    cudaFuncSetAttribute(gemm_mma<EP_BIAS>,     cudaFuncAttributeMaxDynamicSharedMemorySize, GEMM_SMEM);
    cudaFuncSetAttribute(gemm_mma<EP_BIAS_RES>, cudaFuncAttributeMaxDynamicSharedMemorySize, GEMM_SMEM);
    cudaFuncSetAttribute(gemm_mma<EP_GELU>,     cudaFuncAttributeMaxDynamicSharedMemorySize, GEMM_SMEM);
    cudaFuncSetAttribute(gemm_mma<EP_QK>,       cudaFuncAttributeMaxDynamicSharedMemorySize, GEMM_SMEM);

    // weight transposes to [N, K]
    transpose_k<<<dim3(CD / 32, CD / 32), dim3(32, 8)>>>(wq, wqt, CD, CD);
    transpose_k<<<dim3(CD / 32, CD / 32), dim3(32, 8)>>>(wk, wkt, CD, CD);
    transpose_k<<<dim3(CD / 32, CD / 32), dim3(32, 8)>>>(wv, wvt, CD, CD);
    transpose_k<<<dim3(CD / 32, CD / 32), dim3(32, 8)>>>(wo, wot, CD, CD);
    transpose_k<<<dim3(DFF / 32, CD / 32), dim3(32, 8)>>>(w1, w1t, CD, DFF);
    transpose_k<<<dim3(CD / 32, DFF / 32), dim3(32, 8)>>>(w2, w2t, DFF, CD);

    // 1. LN1
    ln_kernel<<<ROWS, 256>>>(x, g1, be1, xn);

    // 2. QKV projections (bf16x3 tensor core)
    gemm_mma<EP_BIAS><<<dim3(CD / 128, ROWS / 128), 256, GEMM_SMEM>>>(
        xn, wqt, bq, nullptr, q, CD, CD, CD, CD, nullptr);
    gemm_mma<EP_BIAS><<<dim3(CD / 128, ROWS / 128), 256, GEMM_SMEM>>>(
        xn, wkt, bk, nullptr, k, CD, CD, CD, CD, nullptr);
    gemm_mma<EP_BIAS><<<dim3(CD / 128, ROWS / 128), 256, GEMM_SMEM>>>(
        xn, wvt, bv, nullptr, v, CD, CD, CD, CD, nullptr);

    // 3. Logits = scale * Q K^T + rel bias (batched over b,h; bf16x3)
    gemm_mma<EP_QK><<<dim3(CN / 128, CN / 128, CB * CH), 256, GEMM_SMEM>>>(
        q, k, nullptr, nullptr, lg, CD, CD, CN, CHD, rel);

    // 4. top-16 + softmax + sparse A@V
    topk_attn<<<dim3(CN, CH, CB), 128>>>(lg, v, att);

    // 5. out proj + residual
    gemm_mma<EP_BIAS_RES><<<dim3(CD / 128, ROWS / 128), 256, GEMM_SMEM>>>(
        att, wot, bo, x, x1, CD, CD, CD, CD, nullptr);

    // 6. LN2
    ln_kernel<<<ROWS, 256>>>(x1, g2, be2, xn);

    // 7. FFN
    gemm_mma<EP_GELU><<<dim3(DFF / 128, ROWS / 128), 256, GEMM_SMEM>>>(
        xn, w1t, bf1, nullptr, ffh, CD, CD, DFF, CD, nullptr);
    gemm_mma<EP_BIAS_RES><<<dim3(CD / 128, ROWS / 128), 256, GEMM_SMEM>>>(
        ffh, w2t, bf2, x1, out, DFF, DFF, CD, DFF, nullptr);
}

// round 9
// speedup vs baseline: 1.5500x; 1.1041x over previous
#include <cuda_runtime.h>
#include <cuda_bf16.h>
#include <cstdint>
#include <math.h>

// Problem constants
constexpr int CB  = 16;
constexpr int CN  = 512;
constexpr int CD  = 512;
constexpr int CH  = 8;
constexpr int CHD = 64;
constexpr int CK  = 16;
constexpr int ROWS = CB * CN;   // 8192
constexpr int DFF  = 4 * CD;    // 2048

// fp32 scratch
__device__ float g_v  [ROWS * CD];
__device__ float g_x1 [ROWS * CD];
__device__ float g_lg [(size_t)CB * CH * CN * CN];
// split bf16 activation scratch (hi/lo error-compensated pairs)
__device__ __nv_bfloat16 g_xnh[ROWS * CD],  g_xnl[ROWS * CD];
__device__ __nv_bfloat16 g_qh [ROWS * CD],  g_ql [ROWS * CD];
__device__ __nv_bfloat16 g_kh [ROWS * CD],  g_kl [ROWS * CD];
__device__ __nv_bfloat16 g_ath[ROWS * CD],  g_atl[ROWS * CD];
__device__ __nv_bfloat16 g_fh [ROWS * DFF], g_fl [ROWS * DFF];
// split transposed weights [N, K]
__device__ __nv_bfloat16 g_wqh[CD * CD],  g_wql[CD * CD];
__device__ __nv_bfloat16 g_wkh[CD * CD],  g_wkl[CD * CD];
__device__ __nv_bfloat16 g_wvh[CD * CD],  g_wvl[CD * CD];
__device__ __nv_bfloat16 g_woh[CD * CD],  g_wol[CD * CD];
__device__ __nv_bfloat16 g_w1h[DFF * CD], g_w1l[DFF * CD];
__device__ __nv_bfloat16 g_w2h[CD * DFF], g_w2l[CD * DFF];

// ---------------------------------------------------------------------------
// helpers (sm_80-class PTX only — compiles at plain target sm_103)
// ---------------------------------------------------------------------------
__device__ __forceinline__ uint32_t smem_u32(const void* p) {
    uint32_t a;
    asm("{ .reg .u64 t; cvta.to.shared.u64 t, %1; cvt.u32.u64 %0, t; }" : "=r"(a) : "l"(p));
    return a;
}
__device__ __forceinline__ void ldsm4(uint32_t* r, uint32_t addr) {
    asm volatile("ldmatrix.sync.aligned.m8n8.x4.shared.b16 {%0,%1,%2,%3}, [%4];"
                 : "=r"(r[0]), "=r"(r[1]), "=r"(r[2]), "=r"(r[3]) : "r"(addr));
}
__device__ __forceinline__ void mma_bf16(float* d, const uint32_t* a,
                                         uint32_t b0, uint32_t b1) {
    asm volatile("mma.sync.aligned.m16n8k16.row.col.f32.bf16.bf16.f32 "
                 "{%0,%1,%2,%3}, {%4,%5,%6,%7}, {%8,%9}, {%0,%1,%2,%3};"
                 : "+f"(d[0]), "+f"(d[1]), "+f"(d[2]), "+f"(d[3])
                 : "r"(a[0]), "r"(a[1]), "r"(a[2]), "r"(a[3]), "r"(b0), "r"(b1));
}
__device__ __forceinline__ void cpa16(uint32_t s, const void* g) {
    asm volatile("cp.async.cg.shared.global [%0], [%1], 16;" :: "r"(s), "l"(g));
}
#define CP_COMMIT() asm volatile("cp.async.commit_group;" ::: "memory")
#define CP_WAIT1()  asm volatile("cp.async.wait_group 1;" ::: "memory")

__device__ __forceinline__ void split2(float x, __nv_bfloat16& h, __nv_bfloat16& l) {
    h = __float2bfloat16_rn(x);
    l = __float2bfloat16_rn(x - __bfloat162float(h));
}

// ---------------------------------------------------------------------------
// bf16x3 tensor-core GEMM on pre-split operands.
// C[M,N] = A[M,K](row) @ B[N,K](row = B^T) + epilogue.
// acc += Ah*Bh + Ah*Bl + Al*Bh (fp32 accum); lo*lo dropped (<=2^-18 rel).
// Block 128x128, BK=32, 256 threads, 8 warps 4x2; warp tile 32x64.
// SMEM stage = [A 16KB][B 16KB]; row 128B = [hi 32bf16 | lo 32bf16], SW128.
// 3 stages, cp.async pipeline, ONE barrier per K-iter.
// ---------------------------------------------------------------------------
enum { EP_BIAS = 0, EP_BIAS_RES = 1, EP_GELU = 2, EP_QK = 3 };
enum { OUT_F32 = 0, OUT_SPLIT = 1 };

constexpr int BK = 32;
constexpr int STAGE2 = 32768;                 // A+B per stage
constexpr int GEMM_SMEM = 3 * STAGE2;         // 98304 B

template <int EPI, int OUTM>
__global__ void __launch_bounds__(256, 2)
gemm_mma(const __nv_bfloat16* __restrict__ Ah, const __nv_bfloat16* __restrict__ Al,
         const __nv_bfloat16* __restrict__ Bh, const __nv_bfloat16* __restrict__ Bl,
         const float* __restrict__ bias, const float* __restrict__ res,
         float* __restrict__ Cf, __nv_bfloat16* __restrict__ Ch,
         __nv_bfloat16* __restrict__ Cl,
         int lda, int ldb, int ldc, int K, const float* __restrict__ rel)
{
    extern __shared__ char smraw[];
    const uint32_t sb = smem_u32(smraw);

    const int tid = threadIdx.x;
    const int lane = tid & 31, wid = tid >> 5;
    const int wm = wid >> 1, wn = wid & 1;       // 4 x 2 warp grid

    const int rowb = blockIdx.y * 128;
    const int colb = blockIdx.x * 128;

    const __nv_bfloat16 *Agh = Ah, *Agl = Al, *Bgh = Bh, *Bgl = Bl;
    float* Cg = Cf;
    int h = 0;
    if (EPI == EP_QK) {
        const int bh = blockIdx.z;
        const int b = bh >> 3; h = bh & 7;
        const size_t off = (size_t)b * CN * CD + h * CHD;
        Agh = Ah + off; Agl = Al + off;
        Bgh = Bh + off; Bgl = Bl + off;
        Cg = Cf + (size_t)bh * CN * CN;
    }

    // ---- cp.async mapping: thread -> (row = tid>>1, half = tid&1 [hi|lo])
    const int grow = tid >> 1;
    const int ghalf = tid & 1;
    const __nv_bfloat16* Asrc = (ghalf ? Agl : Agh) + (size_t)(rowb + grow) * lda;
    const __nv_bfloat16* Bsrc = (ghalf ? Bgl : Bgh) + (size_t)(colb + grow) * ldb;
    uint32_t sdst[4];
    #pragma unroll
    for (int j = 0; j < 4; j++) {
        uint32_t o = (uint32_t)grow * 128u + (uint32_t)ghalf * 64u + (uint32_t)j * 16u;
        sdst[j] = o ^ ((o >> 3) & 0x70u);
    }

    const int NIT = K / BK;
    auto issue = [&](int it) {
        const uint32_t ab = sb + (uint32_t)(it % 3) * STAGE2;
        const uint32_t bb = ab + 16384u;
        const __nv_bfloat16* as = Asrc + it * BK;
        const __nv_bfloat16* bs = Bsrc + it * BK;
        #pragma unroll
        for (int j = 0; j < 4; j++) {
            cpa16(ab + sdst[j], as + j * 8);
            cpa16(bb + sdst[j], bs + j * 8);
        }
    };

    // ---- ldmatrix addressing
    const int lrow16 = lane & 15;
    const uint32_t cg16 = (uint32_t)(lane >> 4) * 16u;
    uint32_t rbA[2], rsA[2], rbB[4], rsB[4];
    #pragma unroll
    for (int mt = 0; mt < 2; mt++) {
        const int r = wm * 32 + mt * 16 + lrow16;
        rbA[mt] = (uint32_t)r * 128u;
        rsA[mt] = (uint32_t)(r & 7) << 4;
    }
    #pragma unroll
    for (int np = 0; np < 4; np++) {
        const int r = wn * 64 + np * 16 + lrow16;
        rbB[np] = (uint32_t)r * 128u;
        rsB[np] = (uint32_t)(r & 7) << 4;
    }

    float acc[2][8][4];
    #pragma unroll
    for (int mt = 0; mt < 2; mt++)
        #pragma unroll
        for (int nt = 0; nt < 8; nt++)
            #pragma unroll
            for (int i = 0; i < 4; i++) acc[mt][nt][i] = 0.0f;

    // prologue: stages 0,1 (always 2 commits to keep group arithmetic uniform)
    issue(0);
    CP_COMMIT();
    if (NIT > 1) issue(1);
    CP_COMMIT();

    for (int it = 0; it < NIT; it++) {
        CP_WAIT1();            // stage `it` landed
        __syncthreads();       // + all warps finished stage it-1 compute
        if (it + 2 < NIT) issue(it + 2);
        CP_COMMIT();           // possibly-empty group keeps counts uniform

        const uint32_t ab = sb + (uint32_t)(it % 3) * STAGE2;
        const uint32_t bb = ab + 16384u;
        #pragma unroll
        for (int ks = 0; ks < 2; ks++) {             // 2 x k16
            const uint32_t kc = (uint32_t)ks * 32u + cg16;
            uint32_t ah[2][4], al[2][4];
            #pragma unroll
            for (int mt = 0; mt < 2; mt++) {
                ldsm4(ah[mt], ab + rbA[mt] + (kc ^ rsA[mt]));
                ldsm4(al[mt], ab + rbA[mt] + ((kc + 64u) ^ rsA[mt]));
            }
            #pragma unroll
            for (int np = 0; np < 4; np++) {
                uint32_t bfh[4], bfl[4];
                ldsm4(bfh, bb + rbB[np] + (kc ^ rsB[np]));
                ldsm4(bfl, bb + rbB[np] + ((kc + 64u) ^ rsB[np]));
                #pragma unroll
                for (int mt = 0; mt < 2; mt++) {
                    mma_bf16(acc[mt][np * 2 + 0], ah[mt], bfh[0], bfh[2]);
                    mma_bf16(acc[mt][np * 2 + 1], ah[mt], bfh[1], bfh[3]);
                    mma_bf16(acc[mt][np * 2 + 0], ah[mt], bfl[0], bfl[2]);
                    mma_bf16(acc[mt][np * 2 + 1], ah[mt], bfl[1], bfl[3]);
                    mma_bf16(acc[mt][np * 2 + 0], al[mt], bfh[0], bfh[2]);
                    mma_bf16(acc[mt][np * 2 + 1], al[mt], bfh[1], bfh[3]);
                }
            }
        }
    }

    // ---- epilogue
    #pragma unroll
    for (int mt = 0; mt < 2; mt++) {
        #pragma unroll
        for (int half = 0; half < 2; half++) {
            const int r = rowb + wm * 32 + mt * 16 + (lane >> 2) + half * 8;
            const float* rrow = (EPI == EP_BIAS_RES) ? res + (size_t)r * ldc : nullptr;
            #pragma unroll
            for (int nt = 0; nt < 8; nt++) {
                const int c = colb + wn * 64 + nt * 8 + (lane & 3) * 2;
                float vx = acc[mt][nt][half * 2 + 0];
                float vy = acc[mt][nt][half * 2 + 1];
                if (EPI == EP_QK) {
                    vx = vx * 0.125f + __ldg(&rel[(size_t)(c     - r + 511) * CH + h]);
                    vy = vy * 0.125f + __ldg(&rel[(size_t)(c + 1 - r + 511) * CH + h]);
                } else {
                    vx += bias[c];
                    vy += bias[c + 1];
                    if (EPI == EP_BIAS_RES) { vx += rrow[c]; vy += rrow[c + 1]; }
                    if (EPI == EP_GELU) {
                        vx = 0.5f * vx * (1.0f + erff(vx * 0.70710678118654752f));
                        vy = 0.5f * vy * (1.0f + erff(vy * 0.70710678118654752f));
                    }
                }
                if (OUTM == OUT_F32) {
                    float2 o; o.x = vx; o.y = vy;
                    *(float2*)(Cg + (size_t)r * ldc + c) = o;
                } else {
                    __nv_bfloat16 hx, lx, hy, ly;
                    split2(vx, hx, lx);
                    split2(vy, hy, ly);
                    *(__nv_bfloat162*)(Ch + (size_t)r * ldc + c) = __halves2bfloat162(hx, hy);
                    *(__nv_bfloat162*)(Cl + (size_t)r * ldc + c) = __halves2bfloat162(lx, ly);
                }
            }
        }
    }
}

// ---------------------------------------------------------------------------
// Weight transpose + split: out_{h,l}[c*R + r] = split(in[r*C + c])
// ---------------------------------------------------------------------------
__global__ void transpose_split(const float* __restrict__ in,
                                __nv_bfloat16* __restrict__ oh,
                                __nv_bfloat16* __restrict__ ol, int R, int C)
{
    __shared__ float t[32][33];
    const int c0 = blockIdx.x * 32, r0 = blockIdx.y * 32;
    const int x = threadIdx.x, y = threadIdx.y;
    #pragma unroll
    for (int i = 0; i < 32; i += 8)
        t[y + i][x] = in[(size_t)(r0 + y + i) * C + c0 + x];
    __syncthreads();
    #pragma unroll
    for (int i = 0; i < 32; i += 8) {
        __nv_bfloat16 h, l;
        split2(t[x][y + i], h, l);
        const size_t o = (size_t)(c0 + y + i) * R + r0 + x;
        oh[o] = h; ol[o] = l;
    }
}

// ---------------------------------------------------------------------------
// LayerNorm, writes split bf16 hi/lo
// ---------------------------------------------------------------------------
__global__ void ln_split(const float* __restrict__ x, const float* __restrict__ g,
                         const float* __restrict__ be,
                         __nv_bfloat16* __restrict__ oh, __nv_bfloat16* __restrict__ ol)
{
    const int row = blockIdx.x;
    const float* xr = x + (size_t)row * CD;
    const int t = threadIdx.x;
    float v0 = xr[t], v1 = xr[t + 256];

    __shared__ float red[256];
    red[t] = v0 + v1;
    __syncthreads();
    #pragma unroll
    for (int o = 128; o > 0; o >>= 1) { if (t < o) red[t] += red[t + o]; __syncthreads(); }
    const float mean = red[0] * (1.0f / CD);
    __syncthreads();

    const float d0 = v0 - mean, d1 = v1 - mean;
    red[t] = d0 * d0 + d1 * d1;
    __syncthreads();
    #pragma unroll
    for (int o = 128; o > 0; o >>= 1) { if (t < o) red[t] += red[t + o]; __syncthreads(); }
    const float var = red[0] * (1.0f / CD);
    const float rs  = rsqrtf(var + 1e-5f);

    const float y0 = d0 * rs * g[t]       + be[t];
    const float y1 = d1 * rs * g[t + 256] + be[t + 256];
    __nv_bfloat16 h, l;
    split2(y0, h, l);
    oh[(size_t)row * CD + t] = h; ol[(size_t)row * CD + t] = l;
    split2(y1, h, l);
    oh[(size_t)row * CD + t + 256] = h; ol[(size_t)row * CD + t + 256] = l;
}

// ---------------------------------------------------------------------------
// Top-16 + softmax + sparse A@V. ONE WARP per (b,h,n) row; zero block barriers.
// Writes split att (feeds out-proj GEMM).
// ---------------------------------------------------------------------------
__global__ void __launch_bounds__(256)
topk_attn(const float* __restrict__ logits, const float* __restrict__ V,
          __nv_bfloat16* __restrict__ oh, __nv_bfloat16* __restrict__ ol)
{
    const int warp = blockIdx.x * 8 + (threadIdx.x >> 5);
    const int lane = threadIdx.x & 31;
    const int n  = warp & (CN - 1);
    const int bh = warp >> 9;
    const int b  = bh >> 3, h = bh & 7;
    const float* row = logits + ((size_t)bh * CN + n) * CN;

    float lv[16];
    #pragma unroll
    for (int j = 0; j < 16; j++) lv[j] = row[j * 32 + lane];

    float topv[CK];
    int   topi[CK];
    #pragma unroll
    for (int it = 0; it < CK; it++) {
        float v = lv[0]; int jj = 0;
        #pragma unroll
        for (int j = 1; j < 16; j++)
            if (lv[j] > v) { v = lv[j]; jj = j; }
        int idx = jj * 32 + lane;
        #pragma unroll
        for (int o = 16; o > 0; o >>= 1) {
            const float v2 = __shfl_xor_sync(0xffffffffu, v, o);
            const int   i2 = __shfl_xor_sync(0xffffffffu, idx, o);
            if (v2 > v || (v2 == v && i2 < idx)) { v = v2; idx = i2; }
        }
        topv[it] = v; topi[it] = idx;
        if ((idx & 31) == lane) {
            const int wj = idx >> 5;
            #pragma unroll
            for (int j = 0; j < 16; j++)
                if (j == wj) lv[j] = -3.0e38f;
        }
    }

    // softmax over selected (topv[0] is the max); all lanes redundantly
    float ex[CK];
    float s = 0.0f;
    #pragma unroll
    for (int i = 0; i < CK; i++) { ex[i] = expf(topv[i] - topv[0]); s += ex[i]; }
    const float inv = 1.0f / s;

    // gather: 64 output cols, 2 per lane
    const float* Vb = V + (size_t)b * CN * CD + h * CHD;
    const size_t obase = ((size_t)(b * CN) + n) * CD + h * CHD;
    #pragma unroll
    for (int cc = 0; cc < 2; cc++) {
        const int c = lane + cc * 32;
        float acc = 0.0f;
        #pragma unroll
        for (int i = 0; i < CK; i++)
            acc += ex[i] * Vb[(size_t)topi[i] * CD + c];
        __nv_bfloat16 hh, ll;
        split2(acc * inv, hh, ll);
        oh[obase + c] = hh; ol[obase + c] = ll;
    }
}

// ---------------------------------------------------------------------------
// Launch
// ---------------------------------------------------------------------------
extern "C" void kernel_launch(void* const* d_in, const int* in_sizes, int n_in,
                              void* d_out, int out_size)
{
    const float* x    = (const float*)d_in[0];
    const float* wq   = (const float*)d_in[1];
    const float* bq   = (const float*)d_in[2];
    const float* wk   = (const float*)d_in[3];
    const float* bk   = (const float*)d_in[4];
    const float* wv   = (const float*)d_in[5];
    const float* bv   = (const float*)d_in[6];
    const float* wo   = (const float*)d_in[7];
    const float* bo   = (const float*)d_in[8];
    const float* g1   = (const float*)d_in[9];
    const float* be1  = (const float*)d_in[10];
    const float* g2   = (const float*)d_in[11];
    const float* be2  = (const float*)d_in[12];
    const float* w1   = (const float*)d_in[13];
    const float* bf1  = (const float*)d_in[14];
    const float* w2   = (const float*)d_in[15];
    const float* bf2  = (const float*)d_in[16];
    const float* rel  = (const float*)d_in[17];
    float* out = (float*)d_out;

    float *v, *x1, *lg;
    __nv_bfloat16 *xnh, *xnl, *qh, *ql, *kh, *kl, *ath, *atl, *fh, *fl;
    __nv_bfloat16 *wqh, *wql, *wkh, *wkl, *wvh, *wvl, *woh, *wol, *w1h, *w1l, *w2h, *w2l;
    cudaGetSymbolAddress((void**)&v,   g_v);
    cudaGetSymbolAddress((void**)&x1,  g_x1);
    cudaGetSymbolAddress((void**)&lg,  g_lg);
    cudaGetSymbolAddress((void**)&xnh, g_xnh);  cudaGetSymbolAddress((void**)&xnl, g_xnl);
    cudaGetSymbolAddress((void**)&qh,  g_qh);   cudaGetSymbolAddress((void**)&ql,  g_ql);
    cudaGetSymbolAddress((void**)&kh,  g_kh);   cudaGetSymbolAddress((void**)&kl,  g_kl);
    cudaGetSymbolAddress((void**)&ath, g_ath);  cudaGetSymbolAddress((void**)&atl, g_atl);
    cudaGetSymbolAddress((void**)&fh,  g_fh);   cudaGetSymbolAddress((void**)&fl,  g_fl);
    cudaGetSymbolAddress((void**)&wqh, g_wqh);  cudaGetSymbolAddress((void**)&wql, g_wql);
    cudaGetSymbolAddress((void**)&wkh, g_wkh);  cudaGetSymbolAddress((void**)&wkl, g_wkl);
    cudaGetSymbolAddress((void**)&wvh, g_wvh);  cudaGetSymbolAddress((void**)&wvl, g_wvl);
    cudaGetSymbolAddress((void**)&woh, g_woh);  cudaGetSymbolAddress((void**)&wol, g_wol);
    cudaGetSymbolAddress((void**)&w1h, g_w1h);  cudaGetSymbolAddress((void**)&w1l, g_w1l);
    cudaGetSymbolAddress((void**)&w2h, g_w2h);  cudaGetSymbolAddress((void**)&w2l, g_w2l);

    cudaFuncSetAttribute(gemm_mma<EP_BIAS, OUT_SPLIT>,     cudaFuncAttributeMaxDynamicSharedMemorySize, GEMM_SMEM);
    cudaFuncSetAttribute(gemm_mma<EP_BIAS, OUT_F32>,       cudaFuncAttributeMaxDynamicSharedMemorySize, GEMM_SMEM);
    cudaFuncSetAttribute(gemm_mma<EP_BIAS_RES, OUT_F32>,   cudaFuncAttributeMaxDynamicSharedMemorySize, GEMM_SMEM);
    cudaFuncSetAttribute(gemm_mma<EP_GELU, OUT_SPLIT>,     cudaFuncAttributeMaxDynamicSharedMemorySize, GEMM_SMEM);
    cudaFuncSetAttribute(gemm_mma<EP_QK, OUT_F32>,         cudaFuncAttributeMaxDynamicSharedMemorySize, GEMM_SMEM);

    // weight transposes + split to [N, K] bf16 hi/lo
    transpose_split<<<dim3(CD / 32, CD / 32), dim3(32, 8)>>>(wq, wqh, wql, CD, CD);
    transpose_split<<<dim3(CD / 32, CD / 32), dim3(32, 8)>>>(wk, wkh, wkl, CD, CD);
    transpose_split<<<dim3(CD / 32, CD / 32), dim3(32, 8)>>>(wv, wvh, wvl, CD, CD);
    transpose_split<<<dim3(CD / 32, CD / 32), dim3(32, 8)>>>(wo, woh, wol, CD, CD);
    transpose_split<<<dim3(DFF / 32, CD / 32), dim3(32, 8)>>>(w1, w1h, w1l, CD, DFF);
    transpose_split<<<dim3(CD / 32, DFF / 32), dim3(32, 8)>>>(w2, w2h, w2l, DFF, CD);

    // 1. LN1 (split output)
    ln_split<<<ROWS, 256>>>(x, g1, be1, xnh, xnl);

    // 2. QKV projections
    gemm_mma<EP_BIAS, OUT_SPLIT><<<dim3(CD / 128, ROWS / 128), 256, GEMM_SMEM>>>(
        xnh, xnl, wqh, wql, bq, nullptr, nullptr, qh, ql, CD, CD, CD, CD, nullptr);
    gemm_mma<EP_BIAS, OUT_SPLIT><<<dim3(CD / 128, ROWS / 128), 256, GEMM_SMEM>>>(
        xnh, xnl, wkh, wkl, bk, nullptr, nullptr, kh, kl, CD, CD, CD, CD, nullptr);
    gemm_mma<EP_BIAS, OUT_F32><<<dim3(CD / 128, ROWS / 128), 256, GEMM_SMEM>>>(
        xnh, xnl, wvh, wvl, bv, nullptr, v, nullptr, nullptr, CD, CD, CD, CD, nullptr);

    // 3. Logits = scale * Q K^T + rel bias (batched over b,h)
    gemm_mma<EP_QK, OUT_F32><<<dim3(CN / 128, CN / 128, CB * CH), 256, GEMM_SMEM>>>(
        qh, ql, kh, kl, nullptr, nullptr, lg, nullptr, nullptr, CD, CD, CN, CHD, rel);

    // 4. top-16 + softmax + sparse A@V (warp per row, split output)
    topk_attn<<<CB * CH * CN / 8, 256>>>(lg, v, ath, atl);

    // 5. out proj + residual
    gemm_mma<EP_BIAS_RES, OUT_F32><<<dim3(CD / 128, ROWS / 128), 256, GEMM_SMEM>>>(
        ath, atl, woh, wol, bo, x, x1, nullptr, nullptr, CD, CD, CD, CD, nullptr);

    // 6. LN2 (split output)
    ln_split<<<ROWS, 256>>>(x1, g2, be2, xnh, xnl);

    // 7. FFN
    gemm_mma<EP_GELU, OUT_SPLIT><<<dim3(DFF / 128, ROWS / 128), 256, GEMM_SMEM>>>(
        xnh, xnl, w1h, w1l, bf1, nullptr, nullptr, fh, fl, CD, CD, DFF, CD, nullptr);
    gemm_mma<EP_BIAS_RES, OUT_F32><<<dim3(CD / 128, ROWS / 128), 256, GEMM_SMEM>>>(
        fh, fl, w2h, w2l, bf2, x1, out, nullptr, nullptr, DFF, DFF, CD, DFF, nullptr);
}

// round 13
// speedup vs baseline: 2.1611x; 1.3943x over previous
#include <cuda_runtime.h>
#include <cuda_bf16.h>
#include <cstdint>
#include <math.h>

// Problem constants
constexpr int CB  = 16;
constexpr int CN  = 512;
constexpr int CD  = 512;
constexpr int CH  = 8;
constexpr int CHD = 64;
constexpr int CK  = 16;
constexpr int ROWS = CB * CN;   // 8192
constexpr int DFF  = 4 * CD;    // 2048

// fp32 scratch
__device__ float g_v  [ROWS * CD];
__device__ float g_att[ROWS * CD];
__device__ float g_x1 [ROWS * CD];
__device__ float g_xnt[ROWS * CD];          // tf32-rounded LN output
__device__ float g_ffh[ROWS * DFF];         // tf32-rounded FFN hidden
__device__ float g_lg [(size_t)CB * CH * CN * CN];
// split bf16 (hi/lo) scratch for the topk-sensitive path
__device__ __nv_bfloat16 g_xnh[ROWS * CD],  g_xnl[ROWS * CD];
__device__ __nv_bfloat16 g_qh [ROWS * CD],  g_ql [ROWS * CD];
__device__ __nv_bfloat16 g_kh [ROWS * CD],  g_kl [ROWS * CD];
// weights: wq|wk transposed+split (bf16x3 path), rest transposed+tf32
__device__ __nv_bfloat16 g_wqkh[2 * CD * CD], g_wqkl[2 * CD * CD];
__device__ float g_wvt[CD * CD];
__device__ float g_wot[CD * CD];
__device__ float g_w1t[DFF * CD];
__device__ float g_w2t[CD * DFF];

// ---------------------------------------------------------------------------
// helpers (sm_80-class PTX only — compiles at plain target sm_103)
// ---------------------------------------------------------------------------
__device__ __forceinline__ uint32_t smem_u32(const void* p) {
    uint32_t a;
    asm("{ .reg .u64 t; cvta.to.shared.u64 t, %1; cvt.u32.u64 %0, t; }" : "=r"(a) : "l"(p));
    return a;
}
__device__ __forceinline__ void ldsm4(uint32_t* r, uint32_t addr) {
    asm volatile("ldmatrix.sync.aligned.m8n8.x4.shared.b16 {%0,%1,%2,%3}, [%4];"
                 : "=r"(r[0]), "=r"(r[1]), "=r"(r[2]), "=r"(r[3]) : "r"(addr));
}
__device__ __forceinline__ void mma_bf16(float* d, const uint32_t* a,
                                         uint32_t b0, uint32_t b1) {
    asm volatile("mma.sync.aligned.m16n8k16.row.col.f32.bf16.bf16.f32 "
                 "{%0,%1,%2,%3}, {%4,%5,%6,%7}, {%8,%9}, {%0,%1,%2,%3};"
                 : "+f"(d[0]), "+f"(d[1]), "+f"(d[2]), "+f"(d[3])
                 : "r"(a[0]), "r"(a[1]), "r"(a[2]), "r"(a[3]), "r"(b0), "r"(b1));
}
__device__ __forceinline__ void mma_tf32(float* d, const uint32_t* a,
                                         uint32_t b0, uint32_t b1) {
    asm volatile("mma.sync.aligned.m16n8k8.row.col.f32.tf32.tf32.f32 "
                 "{%0,%1,%2,%3}, {%4,%5,%6,%7}, {%8,%9}, {%0,%1,%2,%3};"
                 : "+f"(d[0]), "+f"(d[1]), "+f"(d[2]), "+f"(d[3])
                 : "r"(a[0]), "r"(a[1]), "r"(a[2]), "r"(a[3]), "r"(b0), "r"(b1));
}
__device__ __forceinline__ void cpa16(uint32_t s, const void* g) {
    asm volatile("cp.async.cg.shared.global [%0], [%1], 16;" :: "r"(s), "l"(g));
}
#define CP_COMMIT() asm volatile("cp.async.commit_group;" ::: "memory")
#define CP_WAIT1()  asm volatile("cp.async.wait_group 1;" ::: "memory")

__device__ __forceinline__ void split2(float x, __nv_bfloat16& h, __nv_bfloat16& l) {
    h = __float2bfloat16_rn(x);
    l = __float2bfloat16_rn(x - __bfloat162float(h));
}
__device__ __forceinline__ uint32_t f2tf32(float x) {
    uint32_t r;
    asm("cvt.rna.tf32.f32 %0, %1;" : "=r"(r) : "f"(x));
    return r;
}
__device__ __forceinline__ float tf32r(float x) { return __uint_as_float(f2tf32(x)); }

// ---------------------------------------------------------------------------
// Unified tensor-core GEMM.
// DT=0: bf16x3 (A/B given as hi/lo pairs; acc += AhBh + AhBl + AlBh).
// DT=1: single-pass tf32 (A/B given as tf32-rounded f32 buffers).
// C[M,N] = A[M,K](row) @ B[N,K](row = B^T) + epilogue.
// Block 128x128, BK=32, 256 threads, 8 warps 4x2; warp tile 32x64.
// SMEM stage = [A 16KB][B 16KB]; row = 128B; SW128 swizzle; 3 stages cp.async.
// ---------------------------------------------------------------------------
enum { EP_BIAS = 0, EP_BIAS_RES = 1, EP_GELU = 2, EP_QK = 3, EP_QKPROJ = 4 };
enum { OUT_PLAIN = 0, OUT_TF32 = 1, OUT_SPLIT2 = 2 };

constexpr int BK = 32;
constexpr int STAGE2 = 32768;
constexpr int GEMM_SMEM = 3 * STAGE2;   // 98304

template <int DT, int EPI, int OUTM>
__global__ void __launch_bounds__(256, 2)
gemm_mma(const void* A1, const void* A2, const void* B1, const void* B2,
         const float* __restrict__ bias, const float* __restrict__ bias2,
         const float* __restrict__ res,
         float* __restrict__ Cf,
         __nv_bfloat16* __restrict__ Ch,  __nv_bfloat16* __restrict__ Cl,
         __nv_bfloat16* __restrict__ Ch2, __nv_bfloat16* __restrict__ Cl2,
         int lda, int ldb, int ldc, int K, const float* __restrict__ rel)
{
    extern __shared__ char smraw[];
    const uint32_t sb = smem_u32(smraw);

    const int tid = threadIdx.x;
    const int lane = tid & 31, wid = tid >> 5;
    const int wm = wid >> 1, wn = wid & 1;

    const int rowb = blockIdx.y * 128;
    const int colb = blockIdx.x * 128;

    size_t aoff = 0, boff = 0;
    float* Cg = Cf;
    int h = 0;
    if (EPI == EP_QK) {
        const int bh = blockIdx.z;
        const int b = bh >> 3; h = bh & 7;
        aoff = boff = (size_t)b * CN * CD + h * CHD;
        Cg = Cf + (size_t)bh * CN * CN;
    }

    // ---- cp.async mapping
    const int grow = tid >> 1;
    const int ghalf = tid & 1;
    const __nv_bfloat16* Abf = nullptr; const __nv_bfloat16* Bbf = nullptr;
    const float* Af = nullptr; const float* Bf = nullptr;
    if (DT == 0) {
        Abf = (ghalf ? (const __nv_bfloat16*)A2 : (const __nv_bfloat16*)A1)
              + aoff + (size_t)(rowb + grow) * lda;
        Bbf = (ghalf ? (const __nv_bfloat16*)B2 : (const __nv_bfloat16*)B1)
              + boff + (size_t)(colb + grow) * ldb;
    } else {
        Af = (const float*)A1 + aoff + (size_t)(rowb + grow) * lda + ghalf * 16;
        Bf = (const float*)B1 + boff + (size_t)(colb + grow) * ldb + ghalf * 16;
    }
    uint32_t sdst[4];
    #pragma unroll
    for (int j = 0; j < 4; j++) {
        uint32_t o = (uint32_t)grow * 128u + (uint32_t)ghalf * 64u + (uint32_t)j * 16u;
        sdst[j] = o ^ ((o >> 3) & 0x70u);
    }

    const int NIT = K / BK;
    auto issue = [&](int it) {
        const uint32_t ab = sb + (uint32_t)(it % 3) * STAGE2;
        const uint32_t bb = ab + 16384u;
        if (DT == 0) {
            const __nv_bfloat16* as = Abf + it * BK;
            const __nv_bfloat16* bs = Bbf + it * BK;
            #pragma unroll
            for (int j = 0; j < 4; j++) {
                cpa16(ab + sdst[j], as + j * 8);
                cpa16(bb + sdst[j], bs + j * 8);
            }
        } else {
            const float* as = Af + it * BK;
            const float* bs = Bf + it * BK;
            #pragma unroll
            for (int j = 0; j < 4; j++) {
                cpa16(ab + sdst[j], as + j * 4);
                cpa16(bb + sdst[j], bs + j * 4);
            }
        }
    };

    // ---- ldmatrix addressing (identical layout for bf16-k16 and tf32-k8 tiles)
    const int lrow16 = lane & 15;
    const uint32_t cg16 = (uint32_t)(lane >> 4) * 16u;
    uint32_t rbA[2], rsA[2], rbB[4], rsB[4];
    #pragma unroll
    for (int mt = 0; mt < 2; mt++) {
        const int r = wm * 32 + mt * 16 + lrow16;
        rbA[mt] = (uint32_t)r * 128u;
        rsA[mt] = (uint32_t)(r & 7) << 4;
    }
    #pragma unroll
    for (int np = 0; np < 4; np++) {
        const int r = wn * 64 + np * 16 + lrow16;
        rbB[np] = (uint32_t)r * 128u;
        rsB[np] = (uint32_t)(r & 7) << 4;
    }

    float acc[2][8][4];
    #pragma unroll
    for (int mt = 0; mt < 2; mt++)
        #pragma unroll
        for (int nt = 0; nt < 8; nt++)
            #pragma unroll
            for (int i = 0; i < 4; i++) acc[mt][nt][i] = 0.0f;

    issue(0);
    CP_COMMIT();
    if (NIT > 1) issue(1);
    CP_COMMIT();

    for (int it = 0; it < NIT; it++) {
        CP_WAIT1();
        __syncthreads();
        if (it + 2 < NIT) issue(it + 2);
        CP_COMMIT();

        const uint32_t ab = sb + (uint32_t)(it % 3) * STAGE2;
        const uint32_t bb = ab + 16384u;

        if (DT == 0) {
            #pragma unroll
            for (int ks = 0; ks < 2; ks++) {
                const uint32_t kc = (uint32_t)ks * 32u + cg16;
                uint32_t ah[2][4], al[2][4];
                #pragma unroll
                for (int mt = 0; mt < 2; mt++) {
                    ldsm4(ah[mt], ab + rbA[mt] + (kc ^ rsA[mt]));
                    ldsm4(al[mt], ab + rbA[mt] + ((kc + 64u) ^ rsA[mt]));
                }
                #pragma unroll
                for (int np = 0; np < 4; np++) {
                    uint32_t bfh[4], bfl[4];
                    ldsm4(bfh, bb + rbB[np] + (kc ^ rsB[np]));
                    ldsm4(bfl, bb + rbB[np] + ((kc + 64u) ^ rsB[np]));
                    #pragma unroll
                    for (int mt = 0; mt < 2; mt++) {
                        mma_bf16(acc[mt][np * 2 + 0], ah[mt], bfh[0], bfh[2]);
                        mma_bf16(acc[mt][np * 2 + 1], ah[mt], bfh[1], bfh[3]);
                        mma_bf16(acc[mt][np * 2 + 0], ah[mt], bfl[0], bfl[2]);
                        mma_bf16(acc[mt][np * 2 + 1], ah[mt], bfl[1], bfl[3]);
                        mma_bf16(acc[mt][np * 2 + 0], al[mt], bfh[0], bfh[2]);
                        mma_bf16(acc[mt][np * 2 + 1], al[mt], bfh[1], bfh[3]);
                    }
                }
            }
        } else {
            #pragma unroll
            for (int ks = 0; ks < 4; ks++) {           // 4 x k8 tf32
                const uint32_t kc = (uint32_t)ks * 32u + cg16;
                uint32_t af[2][4];
                #pragma unroll
                for (int mt = 0; mt < 2; mt++)
                    ldsm4(af[mt], ab + rbA[mt] + (kc ^ rsA[mt]));
                #pragma unroll
                for (int np = 0; np < 4; np++) {
                    uint32_t bf4[4];
                    ldsm4(bf4, bb + rbB[np] + (kc ^ rsB[np]));
                    #pragma unroll
                    for (int mt = 0; mt < 2; mt++) {
                        mma_tf32(acc[mt][np * 2 + 0], af[mt], bf4[0], bf4[2]);
                        mma_tf32(acc[mt][np * 2 + 1], af[mt], bf4[1], bf4[3]);
                    }
                }
            }
        }
    }

    // ---- epilogue
    const int range = (EPI == EP_QKPROJ) ? (colb >> 9) : 0;   // block-uniform
    const float* biasr = (EPI == EP_QKPROJ && range) ? bias2 : bias;
    __nv_bfloat16* oh = (EPI == EP_QKPROJ) ? (range ? Ch2 : Ch) : Ch;
    __nv_bfloat16* ol = (EPI == EP_QKPROJ) ? (range ? Cl2 : Cl) : Cl;

    #pragma unroll
    for (int mt = 0; mt < 2; mt++) {
        #pragma unroll
        for (int half = 0; half < 2; half++) {
            const int r = rowb + wm * 32 + mt * 16 + (lane >> 2) + half * 8;
            const float* rrow = (EPI == EP_BIAS_RES) ? res + (size_t)r * ldc : nullptr;
            #pragma unroll
            for (int nt = 0; nt < 8; nt++) {
                const int c = colb + wn * 64 + nt * 8 + (lane & 3) * 2;
                float vx = acc[mt][nt][half * 2 + 0];
                float vy = acc[mt][nt][half * 2 + 1];
                if (EPI == EP_QK) {
                    vx = vx * 0.125f + __ldg(&rel[(size_t)(c     - r + 511) * CH + h]);
                    vy = vy * 0.125f + __ldg(&rel[(size_t)(c + 1 - r + 511) * CH + h]);
                    float2 o; o.x = vx; o.y = vy;
                    *(float2*)(Cg + (size_t)r * ldc + c) = o;
                } else if (EPI == EP_QKPROJ) {
                    const int cl = c - (range << 9);
                    vx += biasr[cl];
                    vy += biasr[cl + 1];
                    __nv_bfloat16 hx, lx, hy, ly;
                    split2(vx, hx, lx);
                    split2(vy, hy, ly);
                    *(__nv_bfloat162*)(oh + (size_t)r * CD + cl) = __halves2bfloat162(hx, hy);
                    *(__nv_bfloat162*)(ol + (size_t)r * CD + cl) = __halves2bfloat162(lx, ly);
                } else {
                    vx += bias[c];
                    vy += bias[c + 1];
                    if (EPI == EP_BIAS_RES) { vx += rrow[c]; vy += rrow[c + 1]; }
                    if (EPI == EP_GELU) {
                        vx = 0.5f * vx * (1.0f + erff(vx * 0.70710678118654752f));
                        vy = 0.5f * vy * (1.0f + erff(vy * 0.70710678118654752f));
                    }
                    float2 o;
                    if (OUTM == OUT_TF32) { o.x = tf32r(vx); o.y = tf32r(vy); }
                    else                  { o.x = vx;        o.y = vy;        }
                    *(float2*)(Cg + (size_t)r * ldc + c) = o;
                }
            }
        }
    }
}

// ---------------------------------------------------------------------------
// Transposes
// ---------------------------------------------------------------------------
__global__ void transpose_split_qk(const float* __restrict__ wq,
                                   const float* __restrict__ wk,
                                   __nv_bfloat16* __restrict__ oh,
                                   __nv_bfloat16* __restrict__ ol)
{
    __shared__ float t[32][33];
    const float* in = blockIdx.z ? wk : wq;
    const int rowoff = blockIdx.z * CD;
    const int c0 = blockIdx.x * 32, r0 = blockIdx.y * 32;
    const int x = threadIdx.x, y = threadIdx.y;
    #pragma unroll
    for (int i = 0; i < 32; i += 8)
        t[y + i][x] = in[(size_t)(r0 + y + i) * CD + c0 + x];
    __syncthreads();
    #pragma unroll
    for (int i = 0; i < 32; i += 8) {
        __nv_bfloat16 h, l;
        split2(t[x][y + i], h, l);
        const size_t o = (size_t)(rowoff + c0 + y + i) * CD + r0 + x;
        oh[o] = h; ol[o] = l;
    }
}

__global__ void transpose_tf32(const float* __restrict__ in, float* __restrict__ out,
                               int R, int C)
{
    __shared__ float t[32][33];
    const int c0 = blockIdx.x * 32, r0 = blockIdx.y * 32;
    const int x = threadIdx.x, y = threadIdx.y;
    #pragma unroll
    for (int i = 0; i < 32; i += 8)
        t[y + i][x] = in[(size_t)(r0 + y + i) * C + c0 + x];
    __syncthreads();
    #pragma unroll
    for (int i = 0; i < 32; i += 8)
        out[(size_t)(c0 + y + i) * R + r0 + x] = tf32r(t[x][y + i]);
}

// ---------------------------------------------------------------------------
// LayerNorms
// ---------------------------------------------------------------------------
__global__ void ln1_kernel(const float* __restrict__ x, const float* __restrict__ g,
                           const float* __restrict__ be,
                           __nv_bfloat16* __restrict__ oh, __nv_bfloat16* __restrict__ ol,
                           float* __restrict__ ot)
{
    const int row = blockIdx.x;
    const float* xr = x + (size_t)row * CD;
    const int t = threadIdx.x;
    float v0 = xr[t], v1 = xr[t + 256];

    __shared__ float red[256];
    red[t] = v0 + v1;
    __syncthreads();
    #pragma unroll
    for (int o = 128; o > 0; o >>= 1) { if (t < o) red[t] += red[t + o]; __syncthreads(); }
    const float mean = red[0] * (1.0f / CD);
    __syncthreads();

    const float d0 = v0 - mean, d1 = v1 - mean;
    red[t] = d0 * d0 + d1 * d1;
    __syncthreads();
    #pragma unroll
    for (int o = 128; o > 0; o >>= 1) { if (t < o) red[t] += red[t + o]; __syncthreads(); }
    const float var = red[0] * (1.0f / CD);
    const float rs  = rsqrtf(var + 1e-5f);

    const float y0 = d0 * rs * g[t]       + be[t];
    const float y1 = d1 * rs * g[t + 256] + be[t + 256];
    __nv_bfloat16 h, l;
    split2(y0, h, l);
    oh[(size_t)row * CD + t] = h; ol[(size_t)row * CD + t] = l;
    split2(y1, h, l);
    oh[(size_t)row * CD + t + 256] = h; ol[(size_t)row * CD + t + 256] = l;
    ot[(size_t)row * CD + t]       = tf32r(y0);
    ot[(size_t)row * CD + t + 256] = tf32r(y1);
}

__global__ void ln_tf32(const float* __restrict__ x, const float* __restrict__ g,
                        const float* __restrict__ be, float* __restrict__ ot)
{
    const int row = blockIdx.x;
    const float* xr = x + (size_t)row * CD;
    const int t = threadIdx.x;
    float v0 = xr[t], v1 = xr[t + 256];

    __shared__ float red[256];
    red[t] = v0 + v1;
    __syncthreads();
    #pragma unroll
    for (int o = 128; o > 0; o >>= 1) { if (t < o) red[t] += red[t + o]; __syncthreads(); }
    const float mean = red[0] * (1.0f / CD);
    __syncthreads();

    const float d0 = v0 - mean, d1 = v1 - mean;
    red[t] = d0 * d0 + d1 * d1;
    __syncthreads();
    #pragma unroll
    for (int o = 128; o > 0; o >>= 1) { if (t < o) red[t] += red[t + o]; __syncthreads(); }
    const float var = red[0] * (1.0f / CD);
    const float rs  = rsqrtf(var + 1e-5f);

    ot[(size_t)row * CD + t]       = tf32r(d0 * rs * g[t]       + be[t]);
    ot[(size_t)row * CD + t + 256] = tf32r(d1 * rs * g[t + 256] + be[t + 256]);
}

// ---------------------------------------------------------------------------
// Top-16 + softmax + sparse A@V. One warp per (b,h,n).
// redux-based argmax with cached per-lane maximum (only the winner rescans).
// ---------------------------------------------------------------------------
__device__ __forceinline__ uint32_t okey(float f) {
    const uint32_t u = __float_as_uint(f);
    return (u & 0x80000000u) ? ~u : (u | 0x80000000u);
}

__global__ void __launch_bounds__(256)
topk_attn(const float* __restrict__ logits, const float* __restrict__ V,
          float* __restrict__ out)
{
    const int warp = blockIdx.x * 8 + (threadIdx.x >> 5);
    const int lane = threadIdx.x & 31;
    const int n  = warp & (CN - 1);
    const int bh = warp >> 9;
    const int b  = bh >> 3, h = bh & 7;
    const float* row = logits + ((size_t)bh * CN + n) * CN;

    float lv[16];
    #pragma unroll
    for (int j = 0; j < 16; j++) lv[j] = row[j * 32 + lane];

    // cached per-lane max
    float lmax = lv[0]; int lj = 0;
    #pragma unroll
    for (int j = 1; j < 16; j++)
        if (lv[j] > lmax) { lmax = lv[j]; lj = j; }

    float topv[CK];
    int   topi[CK];
    #pragma unroll
    for (int it = 0; it < CK; it++) {
        const uint32_t key = okey(lmax);
        const uint32_t wk  = __reduce_max_sync(0xffffffffu, key);
        const uint32_t bal = __ballot_sync(0xffffffffu, key == wk);
        const int L = __ffs(bal) - 1;
        topv[it] = __shfl_sync(0xffffffffu, lmax, L);
        topi[it] = __shfl_sync(0xffffffffu, lj, L) * 32 + L;
        if (lane == L) {
            lv[lj] = -3.0e38f;
            lmax = lv[0]; lj = 0;
            #pragma unroll
            for (int j = 1; j < 16; j++)
                if (lv[j] > lmax) { lmax = lv[j]; lj = j; }
        }
    }

    float ex[CK];
    float s = 0.0f;
    #pragma unroll
    for (int i = 0; i < CK; i++) { ex[i] = expf(topv[i] - topv[0]); s += ex[i]; }
    const float inv = 1.0f / s;

    const float* Vb = V + (size_t)b * CN * CD + h * CHD;
    const size_t obase = ((size_t)(b * CN) + n) * CD + h * CHD;
    #pragma unroll
    for (int cc = 0; cc < 2; cc++) {
        const int c = lane + cc * 32;
        float acc = 0.0f;
        #pragma unroll
        for (int i = 0; i < CK; i++)
            acc += ex[i] * Vb[(size_t)topi[i] * CD + c];
        out[obase + c] = tf32r(acc * inv);   // tf32-rounded: feeds out-proj mma
    }
}

// ---------------------------------------------------------------------------
// Launch
// ---------------------------------------------------------------------------
extern "C" void kernel_launch(void* const* d_in, const int* in_sizes, int n_in,
                              void* d_out, int out_size)
{
    const float* x    = (const float*)d_in[0];
    const float* wq   = (const float*)d_in[1];
    const float* bq   = (const float*)d_in[2];
    const float* wk   = (const float*)d_in[3];
    const float* bk   = (const float*)d_in[4];
    const float* wv   = (const float*)d_in[5];
    const float* bv   = (const float*)d_in[6];
    const float* wo   = (const float*)d_in[7];
    const float* bo   = (const float*)d_in[8];
    const float* g1   = (const float*)d_in[9];
    const float* be1  = (const float*)d_in[10];
    const float* g2   = (const float*)d_in[11];
    const float* be2  = (const float*)d_in[12];
    const float* w1   = (const float*)d_in[13];
    const float* bf1  = (const float*)d_in[14];
    const float* w2   = (const float*)d_in[15];
    const float* bf2  = (const float*)d_in[16];
    const float* rel  = (const float*)d_in[17];
    float* out = (float*)d_out;

    float *v, *att, *x1, *xnt, *ffh, *lg, *wvt, *wot, *w1t, *w2t;
    __nv_bfloat16 *xnh, *xnl, *qh, *ql, *kh, *kl, *wqkh, *wqkl;
    cudaGetSymbolAddress((void**)&v,    g_v);
    cudaGetSymbolAddress((void**)&att,  g_att);
    cudaGetSymbolAddress((void**)&x1,   g_x1);
    cudaGetSymbolAddress((void**)&xnt,  g_xnt);
    cudaGetSymbolAddress((void**)&ffh,  g_ffh);
    cudaGetSymbolAddress((void**)&lg,   g_lg);
    cudaGetSymbolAddress((void**)&wvt,  g_wvt);
    cudaGetSymbolAddress((void**)&wot,  g_wot);
    cudaGetSymbolAddress((void**)&w1t,  g_w1t);
    cudaGetSymbolAddress((void**)&w2t,  g_w2t);
    cudaGetSymbolAddress((void**)&xnh,  g_xnh);  cudaGetSymbolAddress((void**)&xnl, g_xnl);
    cudaGetSymbolAddress((void**)&qh,   g_qh);   cudaGetSymbolAddress((void**)&ql,  g_ql);
    cudaGetSymbolAddress((void**)&kh,   g_kh);   cudaGetSymbolAddress((void**)&kl,  g_kl);
    cudaGetSymbolAddress((void**)&wqkh, g_wqkh); cudaGetSymbolAddress((void**)&wqkl, g_wqkl);

    cudaFuncSetAttribute(gemm_mma<0, EP_QKPROJ,  OUT_SPLIT2>, cudaFuncAttributeMaxDynamicSharedMemorySize, GEMM_SMEM);
    cudaFuncSetAttribute(gemm_mma<0, EP_QK,      OUT_PLAIN>,  cudaFuncAttributeMaxDynamicSharedMemorySize, GEMM_SMEM);
    cudaFuncSetAttribute(gemm_mma<1, EP_BIAS,    OUT_PLAIN>,  cudaFuncAttributeMaxDynamicSharedMemorySize, GEMM_SMEM);
    cudaFuncSetAttribute(gemm_mma<1, EP_BIAS_RES,OUT_PLAIN>,  cudaFuncAttributeMaxDynamicSharedMemorySize, GEMM_SMEM);
    cudaFuncSetAttribute(gemm_mma<1, EP_GELU,    OUT_TF32>,   cudaFuncAttributeMaxDynamicSharedMemorySize, GEMM_SMEM);

    // weight prep
    transpose_split_qk<<<dim3(16, 16, 2), dim3(32, 8)>>>(wq, wk, wqkh, wqkl);
    transpose_tf32<<<dim3(16, 16), dim3(32, 8)>>>(wv, wvt, CD, CD);
    transpose_tf32<<<dim3(16, 16), dim3(32, 8)>>>(wo, wot, CD, CD);
    transpose_tf32<<<dim3(64, 16), dim3(32, 8)>>>(w1, w1t, CD, DFF);
    transpose_tf32<<<dim3(16, 64), dim3(32, 8)>>>(w2, w2t, DFF, CD);

    // 1. LN1 (split + tf32 outputs)
    ln1_kernel<<<ROWS, 256>>>(x, g1, be1, xnh, xnl, xnt);

    // 2a. fused Q+K projection (bf16x3, N=1024)
    gemm_mma<0, EP_QKPROJ, OUT_SPLIT2><<<dim3(8, ROWS / 128), 256, GEMM_SMEM>>>(
        xnh, xnl, wqkh, wqkl, bq, bk, nullptr,
        nullptr, qh, ql, kh, kl, CD, CD, CD, CD, nullptr);
    // 2b. V projection (tf32)
    gemm_mma<1, EP_BIAS, OUT_PLAIN><<<dim3(4, ROWS / 128), 256, GEMM_SMEM>>>(
        xnt, nullptr, wvt, nullptr, bv, nullptr, nullptr,
        v, nullptr, nullptr, nullptr, nullptr, CD, CD, CD, CD, nullptr);

    // 3. Logits = scale * Q K^T + rel bias (bf16x3)
    gemm_mma<0, EP_QK, OUT_PLAIN><<<dim3(4, 4, CB * CH), 256, GEMM_SMEM>>>(
        qh, ql, kh, kl, nullptr, nullptr, nullptr,
        lg, nullptr, nullptr, nullptr, nullptr, CD, CD, CN, CHD, rel);

    // 4. top-16 + softmax + sparse A@V
    topk_attn<<<CB * CH * CN / 8, 256>>>(lg, v, att);

    // 5. out proj + residual (tf32)
    gemm_mma<1, EP_BIAS_RES, OUT_PLAIN><<<dim3(4, ROWS / 128), 256, GEMM_SMEM>>>(
        att, nullptr, wot, nullptr, bo, nullptr, x,
        x1, nullptr, nullptr, nullptr, nullptr, CD, CD, CD, CD, nullptr);

    // 6. LN2 (tf32 output)
    ln_tf32<<<ROWS, 256>>>(x1, g2, be2, xnt);

    // 7. FFN (tf32)
    gemm_mma<1, EP_GELU, OUT_TF32><<<dim3(16, ROWS / 128), 256, GEMM_SMEM>>>(
        xnt, nullptr, w1t, nullptr, bf1, nullptr, nullptr,
        ffh, nullptr, nullptr, nullptr, nullptr, CD, CD, DFF, CD, nullptr);
    gemm_mma<1, EP_BIAS_RES, OUT_PLAIN><<<dim3(4, ROWS / 128), 256, GEMM_SMEM>>>(
        ffh, nullptr, w2t, nullptr, bf2, nullptr, x1,
        out, nullptr, nullptr, nullptr, nullptr, DFF, DFF, CD, DFF, nullptr);
}

// round 14
// speedup vs baseline: 2.7661x; 1.2799x over previous
#include <cuda_runtime.h>
#include <cuda_bf16.h>
#include <cuda_fp16.h>
#include <cstdint>
#include <math.h>

// Problem constants
constexpr int CB  = 16;
constexpr int CN  = 512;
constexpr int CD  = 512;
constexpr int CH  = 8;
constexpr int CHD = 64;
constexpr int CK  = 16;
constexpr int ROWS = CB * CN;   // 8192
constexpr int DFF  = 4 * CD;    // 2048

// fp32 scratch
__device__ float g_x1 [ROWS * CD];
__device__ float g_lg [(size_t)CB * CH * CN * CN];
// fp16 linear-path scratch
__device__ __half g_xnf[ROWS * CD];          // LN output (fp16)
__device__ __half g_vf [ROWS * CD];          // V
__device__ __half g_atf[ROWS * CD];          // attention out
__device__ __half g_ffh[ROWS * DFF];         // FFN hidden
// split bf16 (hi/lo) scratch for the topk-sensitive path
__device__ __nv_bfloat16 g_xnh[ROWS * CD],  g_xnl[ROWS * CD];
__device__ __nv_bfloat16 g_qh [ROWS * CD],  g_ql [ROWS * CD];
__device__ __nv_bfloat16 g_kh [ROWS * CD],  g_kl [ROWS * CD];
// weights: wq|wk transposed+split bf16; rest transposed fp16 [N,K]
__device__ __nv_bfloat16 g_wqkh[2 * CD * CD], g_wqkl[2 * CD * CD];
__device__ __half g_wvf[CD * CD];
__device__ __half g_wof[CD * CD];
__device__ __half g_w1f[DFF * CD];
__device__ __half g_w2f[CD * DFF];

// ---------------------------------------------------------------------------
// helpers (sm_80-class PTX only — compiles at plain target sm_103)
// ---------------------------------------------------------------------------
__device__ __forceinline__ uint32_t smem_u32(const void* p) {
    uint32_t a;
    asm("{ .reg .u64 t; cvta.to.shared.u64 t, %1; cvt.u32.u64 %0, t; }" : "=r"(a) : "l"(p));
    return a;
}
__device__ __forceinline__ void ldsm4(uint32_t* r, uint32_t addr) {
    asm volatile("ldmatrix.sync.aligned.m8n8.x4.shared.b16 {%0,%1,%2,%3}, [%4];"
                 : "=r"(r[0]), "=r"(r[1]), "=r"(r[2]), "=r"(r[3]) : "r"(addr));
}
__device__ __forceinline__ void mma_bf16(float* d, const uint32_t* a,
                                         uint32_t b0, uint32_t b1) {
    asm volatile("mma.sync.aligned.m16n8k16.row.col.f32.bf16.bf16.f32 "
                 "{%0,%1,%2,%3}, {%4,%5,%6,%7}, {%8,%9}, {%0,%1,%2,%3};"
                 : "+f"(d[0]), "+f"(d[1]), "+f"(d[2]), "+f"(d[3])
                 : "r"(a[0]), "r"(a[1]), "r"(a[2]), "r"(a[3]), "r"(b0), "r"(b1));
}
__device__ __forceinline__ void mma_f16(float* d, const uint32_t* a,
                                        uint32_t b0, uint32_t b1) {
    asm volatile("mma.sync.aligned.m16n8k16.row.col.f32.f16.f16.f32 "
                 "{%0,%1,%2,%3}, {%4,%5,%6,%7}, {%8,%9}, {%0,%1,%2,%3};"
                 : "+f"(d[0]), "+f"(d[1]), "+f"(d[2]), "+f"(d[3])
                 : "r"(a[0]), "r"(a[1]), "r"(a[2]), "r"(a[3]), "r"(b0), "r"(b1));
}
__device__ __forceinline__ void cpa16(uint32_t s, const void* g) {
    asm volatile("cp.async.cg.shared.global [%0], [%1], 16;" :: "r"(s), "l"(g));
}
#define CP_COMMIT() asm volatile("cp.async.commit_group;" ::: "memory")
#define CP_WAIT1()  asm volatile("cp.async.wait_group 1;" ::: "memory")

__device__ __forceinline__ void split2(float x, __nv_bfloat16& h, __nv_bfloat16& l) {
    h = __float2bfloat16_rn(x);
    l = __float2bfloat16_rn(x - __bfloat162float(h));
}

// ---------------------------------------------------------------------------
// Unified tensor-core GEMM.
// DT=0: bf16x3 (hi/lo pairs; acc += AhBh + AhBl + AlBh). BK=32.
// DT=1: single-pass fp16 (same 11-bit mantissa as tf32, 2x K per mma). BK=64.
// C[M,N] = A[M,K](row) @ B[N,K](row = B^T) + epilogue.
// Block 128x128, 256 threads, 8 warps 4x2; warp tile 32x64.
// SMEM stage = [A 16KB][B 16KB]; row = 128B; SW128 swizzle; 3 stages cp.async.
// ---------------------------------------------------------------------------
enum { EP_BIAS = 0, EP_BIAS_RES = 1, EP_GELU = 2, EP_QK = 3, EP_QKPROJ = 4 };
enum { OUT_PLAIN = 0, OUT_HALF = 1, OUT_SPLIT2 = 2 };

constexpr int STAGE2 = 32768;
constexpr int GEMM_SMEM = 3 * STAGE2;   // 98304

template <int DT, int EPI, int OUTM>
__global__ void __launch_bounds__(256, 2)
gemm_mma(const void* A1, const void* A2, const void* B1, const void* B2,
         const float* __restrict__ bias, const float* __restrict__ bias2,
         const float* __restrict__ res,
         float* __restrict__ Cf, __half* __restrict__ Chf,
         __nv_bfloat16* __restrict__ Ch,  __nv_bfloat16* __restrict__ Cl,
         __nv_bfloat16* __restrict__ Ch2, __nv_bfloat16* __restrict__ Cl2,
         int lda, int ldb, int ldc, int K, const float* __restrict__ rel)
{
    constexpr int BK = (DT == 0) ? 32 : 64;
    extern __shared__ char smraw[];
    const uint32_t sb = smem_u32(smraw);

    const int tid = threadIdx.x;
    const int lane = tid & 31, wid = tid >> 5;
    const int wm = wid >> 1, wn = wid & 1;

    const int rowb = blockIdx.y * 128;
    const int colb = blockIdx.x * 128;

    size_t aoff = 0, boff = 0;
    float* Cg = Cf;
    int h = 0;
    if (EPI == EP_QK) {
        const int bh = blockIdx.z;
        const int b = bh >> 3; h = bh & 7;
        aoff = boff = (size_t)b * CN * CD + h * CHD;
        Cg = Cf + (size_t)bh * CN * CN;
    }

    // ---- cp.async mapping: thread -> (row = tid>>1, half-chunk = tid&1)
    const int grow = tid >> 1;
    const int ghalf = tid & 1;
    const __nv_bfloat16* Abf = nullptr; const __nv_bfloat16* Bbf = nullptr;
    const __half* Ahp = nullptr; const __half* Bhp = nullptr;
    if (DT == 0) {
        Abf = (ghalf ? (const __nv_bfloat16*)A2 : (const __nv_bfloat16*)A1)
              + aoff + (size_t)(rowb + grow) * lda;
        Bbf = (ghalf ? (const __nv_bfloat16*)B2 : (const __nv_bfloat16*)B1)
              + boff + (size_t)(colb + grow) * ldb;
    } else {
        Ahp = (const __half*)A1 + aoff + (size_t)(rowb + grow) * lda + ghalf * 32;
        Bhp = (const __half*)B1 + boff + (size_t)(colb + grow) * ldb + ghalf * 32;
    }
    uint32_t sdst[4];
    #pragma unroll
    for (int j = 0; j < 4; j++) {
        uint32_t o = (uint32_t)grow * 128u + (uint32_t)ghalf * 64u + (uint32_t)j * 16u;
        sdst[j] = o ^ ((o >> 3) & 0x70u);
    }

    const int NIT = K / BK;
    auto issue = [&](int it) {
        const uint32_t ab = sb + (uint32_t)(it % 3) * STAGE2;
        const uint32_t bb = ab + 16384u;
        if (DT == 0) {
            const __nv_bfloat16* as = Abf + it * BK;
            const __nv_bfloat16* bs = Bbf + it * BK;
            #pragma unroll
            for (int j = 0; j < 4; j++) {
                cpa16(ab + sdst[j], as + j * 8);
                cpa16(bb + sdst[j], bs + j * 8);
            }
        } else {
            const __half* as = Ahp + it * BK;
            const __half* bs = Bhp + it * BK;
            #pragma unroll
            for (int j = 0; j < 4; j++) {
                cpa16(ab + sdst[j], as + j * 8);
                cpa16(bb + sdst[j], bs + j * 8);
            }
        }
    };

    // ---- ldmatrix addressing
    const int lrow16 = lane & 15;
    const uint32_t cg16 = (uint32_t)(lane >> 4) * 16u;
    uint32_t rbA[2], rsA[2], rbB[4], rsB[4];
    #pragma unroll
    for (int mt = 0; mt < 2; mt++) {
        const int r = wm * 32 + mt * 16 + lrow16;
        rbA[mt] = (uint32_t)r * 128u;
        rsA[mt] = (uint32_t)(r & 7) << 4;
    }
    #pragma unroll
    for (int np = 0; np < 4; np++) {
        const int r = wn * 64 + np * 16 + lrow16;
        rbB[np] = (uint32_t)r * 128u;
        rsB[np] = (uint32_t)(r & 7) << 4;
    }

    float acc[2][8][4];
    #pragma unroll
    for (int mt = 0; mt < 2; mt++)
        #pragma unroll
        for (int nt = 0; nt < 8; nt++)
            #pragma unroll
            for (int i = 0; i < 4; i++) acc[mt][nt][i] = 0.0f;

    issue(0);
    CP_COMMIT();
    if (NIT > 1) issue(1);
    CP_COMMIT();

    for (int it = 0; it < NIT; it++) {
        CP_WAIT1();
        __syncthreads();
        if (it + 2 < NIT) issue(it + 2);
        CP_COMMIT();

        const uint32_t ab = sb + (uint32_t)(it % 3) * STAGE2;
        const uint32_t bb = ab + 16384u;

        if (DT == 0) {
            #pragma unroll
            for (int ks = 0; ks < 2; ks++) {
                const uint32_t kc = (uint32_t)ks * 32u + cg16;
                uint32_t ah[2][4], al[2][4];
                #pragma unroll
                for (int mt = 0; mt < 2; mt++) {
                    ldsm4(ah[mt], ab + rbA[mt] + (kc ^ rsA[mt]));
                    ldsm4(al[mt], ab + rbA[mt] + ((kc + 64u) ^ rsA[mt]));
                }
                #pragma unroll
                for (int np = 0; np < 4; np++) {
                    uint32_t bfh[4], bfl[4];
                    ldsm4(bfh, bb + rbB[np] + (kc ^ rsB[np]));
                    ldsm4(bfl, bb + rbB[np] + ((kc + 64u) ^ rsB[np]));
                    #pragma unroll
                    for (int mt = 0; mt < 2; mt++) {
                        mma_bf16(acc[mt][np * 2 + 0], ah[mt], bfh[0], bfh[2]);
                        mma_bf16(acc[mt][np * 2 + 1], ah[mt], bfh[1], bfh[3]);
                        mma_bf16(acc[mt][np * 2 + 0], ah[mt], bfl[0], bfl[2]);
                        mma_bf16(acc[mt][np * 2 + 1], ah[mt], bfl[1], bfl[3]);
                        mma_bf16(acc[mt][np * 2 + 0], al[mt], bfh[0], bfh[2]);
                        mma_bf16(acc[mt][np * 2 + 1], al[mt], bfh[1], bfh[3]);
                    }
                }
            }
        } else {
            #pragma unroll
            for (int ks = 0; ks < 4; ks++) {           // 4 x k16 fp16
                const uint32_t kc = (uint32_t)ks * 32u + cg16;
                uint32_t af[2][4];
                #pragma unroll
                for (int mt = 0; mt < 2; mt++)
                    ldsm4(af[mt], ab + rbA[mt] + (kc ^ rsA[mt]));
                #pragma unroll
                for (int np = 0; np < 4; np++) {
                    uint32_t bf4[4];
                    ldsm4(bf4, bb + rbB[np] + (kc ^ rsB[np]));
                    #pragma unroll
                    for (int mt = 0; mt < 2; mt++) {
                        mma_f16(acc[mt][np * 2 + 0], af[mt], bf4[0], bf4[2]);
                        mma_f16(acc[mt][np * 2 + 1], af[mt], bf4[1], bf4[3]);
                    }
                }
            }
        }
    }

    // ---- epilogue
    const int range = (EPI == EP_QKPROJ) ? (colb >> 9) : 0;   // block-uniform
    const float* biasr = (EPI == EP_QKPROJ && range) ? bias2 : bias;
    __nv_bfloat16* oh = (EPI == EP_QKPROJ) ? (range ? Ch2 : Ch) : Ch;
    __nv_bfloat16* ol = (EPI == EP_QKPROJ) ? (range ? Cl2 : Cl) : Cl;

    #pragma unroll
    for (int mt = 0; mt < 2; mt++) {
        #pragma unroll
        for (int half = 0; half < 2; half++) {
            const int r = rowb + wm * 32 + mt * 16 + (lane >> 2) + half * 8;
            const float* rrow = (EPI == EP_BIAS_RES) ? res + (size_t)r * ldc : nullptr;
            #pragma unroll
            for (int nt = 0; nt < 8; nt++) {
                const int c = colb + wn * 64 + nt * 8 + (lane & 3) * 2;
                float vx = acc[mt][nt][half * 2 + 0];
                float vy = acc[mt][nt][half * 2 + 1];
                if (EPI == EP_QK) {
                    vx = vx * 0.125f + __ldg(&rel[(size_t)(c     - r + 511) * CH + h]);
                    vy = vy * 0.125f + __ldg(&rel[(size_t)(c + 1 - r + 511) * CH + h]);
                    float2 o; o.x = vx; o.y = vy;
                    *(float2*)(Cg + (size_t)r * ldc + c) = o;
                } else if (EPI == EP_QKPROJ) {
                    const int cl = c - (range << 9);
                    vx += biasr[cl];
                    vy += biasr[cl + 1];
                    __nv_bfloat16 hx, lx, hy, ly;
                    split2(vx, hx, lx);
                    split2(vy, hy, ly);
                    *(__nv_bfloat162*)(oh + (size_t)r * CD + cl) = __halves2bfloat162(hx, hy);
                    *(__nv_bfloat162*)(ol + (size_t)r * CD + cl) = __halves2bfloat162(lx, ly);
                } else {
                    vx += bias[c];
                    vy += bias[c + 1];
                    if (EPI == EP_BIAS_RES) { vx += rrow[c]; vy += rrow[c + 1]; }
                    if (EPI == EP_GELU) {
                        vx = 0.5f * vx * (1.0f + erff(vx * 0.70710678118654752f));
                        vy = 0.5f * vy * (1.0f + erff(vy * 0.70710678118654752f));
                    }
                    if (OUTM == OUT_HALF) {
                        *(__half2*)(Chf + (size_t)r * ldc + c) = __floats2half2_rn(vx, vy);
                    } else {
                        float2 o; o.x = vx; o.y = vy;
                        *(float2*)(Cg + (size_t)r * ldc + c) = o;
                    }
                }
            }
        }
    }
}

// ---------------------------------------------------------------------------
// Transposes
// ---------------------------------------------------------------------------
__global__ void transpose_split_qk(const float* __restrict__ wq,
                                   const float* __restrict__ wk,
                                   __nv_bfloat16* __restrict__ oh,
                                   __nv_bfloat16* __restrict__ ol)
{
    __shared__ float t[32][33];
    const float* in = blockIdx.z ? wk : wq;
    const int rowoff = blockIdx.z * CD;
    const int c0 = blockIdx.x * 32, r0 = blockIdx.y * 32;
    const int x = threadIdx.x, y = threadIdx.y;
    #pragma unroll
    for (int i = 0; i < 32; i += 8)
        t[y + i][x] = in[(size_t)(r0 + y + i) * CD + c0 + x];
    __syncthreads();
    #pragma unroll
    for (int i = 0; i < 32; i += 8) {
        __nv_bfloat16 h, l;
        split2(t[x][y + i], h, l);
        const size_t o = (size_t)(rowoff + c0 + y + i) * CD + r0 + x;
        oh[o] = h; ol[o] = l;
    }
}

__global__ void transpose_half(const float* __restrict__ in, __half* __restrict__ out,
                               int R, int C)
{
    __shared__ float t[32][33];
    const int c0 = blockIdx.x * 32, r0 = blockIdx.y * 32;
    const int x = threadIdx.x, y = threadIdx.y;
    #pragma unroll
    for (int i = 0; i < 32; i += 8)
        t[y + i][x] = in[(size_t)(r0 + y + i) * C + c0 + x];
    __syncthreads();
    #pragma unroll
    for (int i = 0; i < 32; i += 8)
        out[(size_t)(c0 + y + i) * R + r0 + x] = __float2half_rn(t[x][y + i]);
}

// ---------------------------------------------------------------------------
// LayerNorms
// ---------------------------------------------------------------------------
__global__ void ln1_kernel(const float* __restrict__ x, const float* __restrict__ g,
                           const float* __restrict__ be,
                           __nv_bfloat16* __restrict__ oh, __nv_bfloat16* __restrict__ ol,
                           __half* __restrict__ of)
{
    const int row = blockIdx.x;
    const float* xr = x + (size_t)row * CD;
    const int t = threadIdx.x;
    float v0 = xr[t], v1 = xr[t + 256];

    __shared__ float red[256];
    red[t] = v0 + v1;
    __syncthreads();
    #pragma unroll
    for (int o = 128; o > 0; o >>= 1) { if (t < o) red[t] += red[t + o]; __syncthreads(); }
    const float mean = red[0] * (1.0f / CD);
    __syncthreads();

    const float d0 = v0 - mean, d1 = v1 - mean;
    red[t] = d0 * d0 + d1 * d1;
    __syncthreads();
    #pragma unroll
    for (int o = 128; o > 0; o >>= 1) { if (t < o) red[t] += red[t + o]; __syncthreads(); }
    const float var = red[0] * (1.0f / CD);
    const float rs  = rsqrtf(var + 1e-5f);

    const float y0 = d0 * rs * g[t]       + be[t];
    const float y1 = d1 * rs * g[t + 256] + be[t + 256];
    __nv_bfloat16 h, l;
    split2(y0, h, l);
    oh[(size_t)row * CD + t] = h; ol[(size_t)row * CD + t] = l;
    split2(y1, h, l);
    oh[(size_t)row * CD + t + 256] = h; ol[(size_t)row * CD + t + 256] = l;
    of[(size_t)row * CD + t]       = __float2half_rn(y0);
    of[(size_t)row * CD + t + 256] = __float2half_rn(y1);
}

__global__ void ln_half(const float* __restrict__ x, const float* __restrict__ g,
                        const float* __restrict__ be, __half* __restrict__ of)
{
    const int row = blockIdx.x;
    const float* xr = x + (size_t)row * CD;
    const int t = threadIdx.x;
    float v0 = xr[t], v1 = xr[t + 256];

    __shared__ float red[256];
    red[t] = v0 + v1;
    __syncthreads();
    #pragma unroll
    for (int o = 128; o > 0; o >>= 1) { if (t < o) red[t] += red[t + o]; __syncthreads(); }
    const float mean = red[0] * (1.0f / CD);
    __syncthreads();

    const float d0 = v0 - mean, d1 = v1 - mean;
    red[t] = d0 * d0 + d1 * d1;
    __syncthreads();
    #pragma unroll
    for (int o = 128; o > 0; o >>= 1) { if (t < o) red[t] += red[t + o]; __syncthreads(); }
    const float var = red[0] * (1.0f / CD);
    const float rs  = rsqrtf(var + 1e-5f);

    of[(size_t)row * CD + t]       = __float2half_rn(d0 * rs * g[t]       + be[t]);
    of[(size_t)row * CD + t + 256] = __float2half_rn(d1 * rs * g[t + 256] + be[t + 256]);
}

// ---------------------------------------------------------------------------
// Top-16 + softmax + sparse A@V. One warp per (b,h,n).
// ---------------------------------------------------------------------------
__device__ __forceinline__ uint32_t okey(float f) {
    const uint32_t u = __float_as_uint(f);
    return (u & 0x80000000u) ? ~u : (u | 0x80000000u);
}

__global__ void __launch_bounds__(256)
topk_attn(const float* __restrict__ logits, const __half* __restrict__ V,
          __half* __restrict__ out)
{
    const int warp = blockIdx.x * 8 + (threadIdx.x >> 5);
    const int lane = threadIdx.x & 31;
    const int n  = warp & (CN - 1);
    const int bh = warp >> 9;
    const int b  = bh >> 3, h = bh & 7;
    const float* row = logits + ((size_t)bh * CN + n) * CN;

    float lv[16];
    #pragma unroll
    for (int j = 0; j < 16; j++) lv[j] = row[j * 32 + lane];

    float lmax = lv[0]; int lj = 0;
    #pragma unroll
    for (int j = 1; j < 16; j++)
        if (lv[j] > lmax) { lmax = lv[j]; lj = j; }

    float topv[CK];
    int   topi[CK];
    #pragma unroll
    for (int it = 0; it < CK; it++) {
        const uint32_t key = okey(lmax);
        const uint32_t wk  = __reduce_max_sync(0xffffffffu, key);
        const uint32_t bal = __ballot_sync(0xffffffffu, key == wk);
        const int L = __ffs(bal) - 1;
        topv[it] = __shfl_sync(0xffffffffu, lmax, L);
        topi[it] = __shfl_sync(0xffffffffu, lj, L) * 32 + L;
        if (lane == L) {
            lv[lj] = -3.0e38f;
            lmax = lv[0]; lj = 0;
            #pragma unroll
            for (int j = 1; j < 16; j++)
                if (lv[j] > lmax) { lmax = lv[j]; lj = j; }
        }
    }

    float ex[CK];
    float s = 0.0f;
    #pragma unroll
    for (int i = 0; i < CK; i++) { ex[i] = expf(topv[i] - topv[0]); s += ex[i]; }
    const float inv = 1.0f / s;

    const __half* Vb = V + (size_t)b * CN * CD + h * CHD;
    const size_t obase = ((size_t)(b * CN) + n) * CD + h * CHD;
    #pragma unroll
    for (int cc = 0; cc < 2; cc++) {
        const int c = lane + cc * 32;
        float acc = 0.0f;
        #pragma unroll
        for (int i = 0; i < CK; i++)
            acc += ex[i] * __half2float(Vb[(size_t)topi[i] * CD + c]);
        out[obase + c] = __float2half_rn(acc * inv);
    }
}

// ---------------------------------------------------------------------------
// Launch
// ---------------------------------------------------------------------------
extern "C" void kernel_launch(void* const* d_in, const int* in_sizes, int n_in,
                              void* d_out, int out_size)
{
    const float* x    = (const float*)d_in[0];
    const float* wq   = (const float*)d_in[1];
    const float* bq   = (const float*)d_in[2];
    const float* wk   = (const float*)d_in[3];
    const float* bk   = (const float*)d_in[4];
    const float* wv   = (const float*)d_in[5];
    const float* bv   = (const float*)d_in[6];
    const float* wo   = (const float*)d_in[7];
    const float* bo   = (const float*)d_in[8];
    const float* g1   = (const float*)d_in[9];
    const float* be1  = (const float*)d_in[10];
    const float* g2   = (const float*)d_in[11];
    const float* be2  = (const float*)d_in[12];
    const float* w1   = (const float*)d_in[13];
    const float* bf1  = (const float*)d_in[14];
    const float* w2   = (const float*)d_in[15];
    const float* bf2  = (const float*)d_in[16];
    const float* rel  = (const float*)d_in[17];
    float* out = (float*)d_out;

    float *x1, *lg;
    __half *xnf, *vf, *atf, *ffh, *wvf, *wof, *w1f, *w2f;
    __nv_bfloat16 *xnh, *xnl, *qh, *ql, *kh, *kl, *wqkh, *wqkl;
    cudaGetSymbolAddress((void**)&x1,   g_x1);
    cudaGetSymbolAddress((void**)&lg,   g_lg);
    cudaGetSymbolAddress((void**)&xnf,  g_xnf);
    cudaGetSymbolAddress((void**)&vf,   g_vf);
    cudaGetSymbolAddress((void**)&atf,  g_atf);
    cudaGetSymbolAddress((void**)&ffh,  g_ffh);
    cudaGetSymbolAddress((void**)&wvf,  g_wvf);
    cudaGetSymbolAddress((void**)&wof,  g_wof);
    cudaGetSymbolAddress((void**)&w1f,  g_w1f);
    cudaGetSymbolAddress((void**)&w2f,  g_w2f);
    cudaGetSymbolAddress((void**)&xnh,  g_xnh);  cudaGetSymbolAddress((void**)&xnl, g_xnl);
    cudaGetSymbolAddress((void**)&qh,   g_qh);   cudaGetSymbolAddress((void**)&ql,  g_ql);
    cudaGetSymbolAddress((void**)&kh,   g_kh);   cudaGetSymbolAddress((void**)&kl,  g_kl);
    cudaGetSymbolAddress((void**)&wqkh, g_wqkh); cudaGetSymbolAddress((void**)&wqkl, g_wqkl);

    cudaFuncSetAttribute(gemm_mma<0, EP_QKPROJ,  OUT_SPLIT2>, cudaFuncAttributeMaxDynamicSharedMemorySize, GEMM_SMEM);
    cudaFuncSetAttribute(gemm_mma<0, EP_QK,      OUT_PLAIN>,  cudaFuncAttributeMaxDynamicSharedMemorySize, GEMM_SMEM);
    cudaFuncSetAttribute(gemm_mma<1, EP_BIAS,    OUT_HALF>,   cudaFuncAttributeMaxDynamicSharedMemorySize, GEMM_SMEM);
    cudaFuncSetAttribute(gemm_mma<1, EP_BIAS_RES,OUT_PLAIN>,  cudaFuncAttributeMaxDynamicSharedMemorySize, GEMM_SMEM);
    cudaFuncSetAttribute(gemm_mma<1, EP_GELU,    OUT_HALF>,   cudaFuncAttributeMaxDynamicSharedMemorySize, GEMM_SMEM);

    // weight prep
    transpose_split_qk<<<dim3(16, 16, 2), dim3(32, 8)>>>(wq, wk, wqkh, wqkl);
    transpose_half<<<dim3(16, 16), dim3(32, 8)>>>(wv, wvf, CD, CD);
    transpose_half<<<dim3(16, 16), dim3(32, 8)>>>(wo, wof, CD, CD);
    transpose_half<<<dim3(64, 16), dim3(32, 8)>>>(w1, w1f, CD, DFF);
    transpose_half<<<dim3(16, 64), dim3(32, 8)>>>(w2, w2f, DFF, CD);

    // 1. LN1 (split bf16 + fp16 outputs)
    ln1_kernel<<<ROWS, 256>>>(x, g1, be1, xnh, xnl, xnf);

    // 2a. fused Q+K projection (bf16x3, N=1024)
    gemm_mma<0, EP_QKPROJ, OUT_SPLIT2><<<dim3(8, ROWS / 128), 256, GEMM_SMEM>>>(
        xnh, xnl, wqkh, wqkl, bq, bk, nullptr,
        nullptr, nullptr, qh, ql, kh, kl, CD, CD, CD, CD, nullptr);
    // 2b. V projection (fp16)
    gemm_mma<1, EP_BIAS, OUT_HALF><<<dim3(4, ROWS / 128), 256, GEMM_SMEM>>>(
        xnf, nullptr, wvf, nullptr, bv, nullptr, nullptr,
        nullptr, vf, nullptr, nullptr, nullptr, nullptr, CD, CD, CD, CD, nullptr);

    // 3. Logits = scale * Q K^T + rel bias (bf16x3)
    gemm_mma<0, EP_QK, OUT_PLAIN><<<dim3(4, 4, CB * CH), 256, GEMM_SMEM>>>(
        qh, ql, kh, kl, nullptr, nullptr, nullptr,
        lg, nullptr, nullptr, nullptr, nullptr, nullptr, CD, CD, CN, CHD, rel);

    // 4. top-16 + softmax + sparse A@V
    topk_attn<<<CB * CH * CN / 8, 256>>>(lg, vf, atf);

    // 5. out proj + residual (fp16)
    gemm_mma<1, EP_BIAS_RES, OUT_PLAIN><<<dim3(4, ROWS / 128), 256, GEMM_SMEM>>>(
        atf, nullptr, wof, nullptr, bo, nullptr, x,
        x1, nullptr, nullptr, nullptr, nullptr, nullptr, CD, CD, CD, CD, nullptr);

    // 6. LN2 (fp16 output)
    ln_half<<<ROWS, 256>>>(x1, g2, be2, xnf);

    // 7. FFN (fp16)
    gemm_mma<1, EP_GELU, OUT_HALF><<<dim3(16, ROWS / 128), 256, GEMM_SMEM>>>(
        xnf, nullptr, w1f, nullptr, bf1, nullptr, nullptr,
        nullptr, ffh, nullptr, nullptr, nullptr, nullptr, CD, CD, DFF, CD, nullptr);
    gemm_mma<1, EP_BIAS_RES, OUT_PLAIN><<<dim3(4, ROWS / 128), 256, GEMM_SMEM>>>(
        ffh, nullptr, w2f, nullptr, bf2, nullptr, x1,
        out, nullptr, nullptr, nullptr, nullptr, nullptr, DFF, DFF, CD, DFF, nullptr);
}